// round 10
// baseline (speedup 1.0000x reference)
#include <cuda_runtime.h>
#include <cuda_fp16.h>
#include <cstdint>

#define SEQ 2048
#define HID 4096
#define NH  32
#define NKV 8
#define HD  128
#define SCALE 0.08838834764831845f

// ---------------- scratch (device globals; no allocations) ----------------
__device__ __half g_Xh  [(size_t)SEQ * HID];
__device__ __half g_Xl  [(size_t)SEQ * HID];
__device__ __half g_Wqkv[(size_t)HID * 6144];   // [Wq | Wk | Wv] fp16, [K=4096, N=6144]
__device__ __half g_Woh [(size_t)4096 * HID];   // Wo fp16 [K=4096, N=4096]
__device__ float  g_qkvf[(size_t)SEQ * 6144];
__device__ __half g_qh  [(size_t)SEQ * 4096];
__device__ __half g_ql  [(size_t)SEQ * 4096];
__device__ __half g_kh  [(size_t)SEQ * 1024];
__device__ __half g_vh  [(size_t)SEQ * 1024];
__device__ __half g_vl  [(size_t)SEQ * 1024];
__device__ __half g_ath [(size_t)SEQ * 4096];
__device__ __half g_atl [(size_t)SEQ * 4096];

// ---------------- helpers ----------------
__device__ __forceinline__ uint32_t smem_u32(const void* p) {
    return (uint32_t)__cvta_generic_to_shared(p);
}
__device__ __forceinline__ void cp16(uint32_t s, const void* g) {
    asm volatile("cp.async.cg.shared.global [%0], [%1], 16;\n" :: "r"(s), "l"(g));
}
#define CP_COMMIT() asm volatile("cp.async.commit_group;")
#define CP_WAIT(n)  asm volatile("cp.async.wait_group %0;" :: "n"(n))

__device__ __forceinline__ void ldsm4(uint32_t* r, uint32_t a) {
    asm volatile("ldmatrix.sync.aligned.m8n8.x4.shared.b16 {%0,%1,%2,%3}, [%4];"
                 : "=r"(r[0]), "=r"(r[1]), "=r"(r[2]), "=r"(r[3]) : "r"(a));
}
__device__ __forceinline__ void ldsm4t(uint32_t* r, uint32_t a) {
    asm volatile("ldmatrix.sync.aligned.m8n8.x4.trans.shared.b16 {%0,%1,%2,%3}, [%4];"
                 : "=r"(r[0]), "=r"(r[1]), "=r"(r[2]), "=r"(r[3]) : "r"(a));
}
__device__ __forceinline__ void mma_f16(float* c, const uint32_t* a, const uint32_t* b) {
    asm volatile("mma.sync.aligned.m16n8k16.row.col.f32.f16.f16.f32 "
                 "{%0,%1,%2,%3},{%4,%5,%6,%7},{%8,%9},{%0,%1,%2,%3};"
                 : "+f"(c[0]), "+f"(c[1]), "+f"(c[2]), "+f"(c[3])
                 : "r"(a[0]), "r"(a[1]), "r"(a[2]), "r"(a[3]), "r"(b[0]), "r"(b[1]));
}
__device__ __forceinline__ uint32_t pack_h2(float a, float b) {
    __half2 t = __floats2half2_rn(a, b);
    return *reinterpret_cast<uint32_t*>(&t);
}

// ---------------- prep kernels ----------------
__global__ void split2_kernel(const float* __restrict__ s, __half* __restrict__ h,
                              __half* __restrict__ l, int n) {
    for (int i = blockIdx.x * blockDim.x + threadIdx.x; i < n; i += gridDim.x * blockDim.x) {
        float x = s[i];
        __half hh = __float2half_rn(x);
        h[i] = hh;
        l[i] = __float2half_rn(x - __half2float(hh));
    }
}
// pack [Wq | Wk | Wv] -> Wqkv[k][0..6143] fp16
__global__ void wqkv_pack(const float* __restrict__ Wq, const float* __restrict__ Wk,
                          const float* __restrict__ Wv, __half* __restrict__ d) {
    const int n = HID * 6144;
    for (int i = blockIdx.x * blockDim.x + threadIdx.x; i < n; i += gridDim.x * blockDim.x) {
        int r = i / 6144, c = i - r * 6144;
        float x;
        if (c < 4096)      x = Wq[(size_t)r * 4096 + c];
        else if (c < 5120) x = Wk[(size_t)r * 1024 + (c - 4096)];
        else               x = Wv[(size_t)r * 1024 + (c - 5120)];
        d[i] = __float2half_rn(x);
    }
}
__global__ void split1_kernel(const float* __restrict__ s, __half* __restrict__ d, int n) {
    for (int i = blockIdx.x * blockDim.x + threadIdx.x; i < n; i += gridDim.x * blockDim.x)
        d[i] = __float2half_rn(s[i]);
}
__global__ void vsplit_kernel(const float* __restrict__ qkvf, __half* __restrict__ vh,
                              __half* __restrict__ vl) {
    int n = SEQ * 1024;
    for (int i = blockIdx.x * blockDim.x + threadIdx.x; i < n; i += gridDim.x * blockDim.x) {
        int r = i >> 10, c = i & 1023;
        float x = qkvf[(size_t)r * 6144 + 5120 + c];
        __half hh = __float2half_rn(x);
        vh[i] = hh;
        vl[i] = __float2half_rn(x - __half2float(hh));
    }
}
__global__ void rope_split_kernel(const float* __restrict__ qkvf,
                                  const float* __restrict__ cosb, const float* __restrict__ sinb,
                                  __half* __restrict__ qh, __half* __restrict__ ql,
                                  __half* __restrict__ kh)
{
    int gw = blockIdx.x * 8 + (threadIdx.x >> 5);
    int lane = threadIdx.x & 31;
    int s = gw / 40, hh = gw % 40;
    if (s >= SEQ) return;

    float c0 = cosb[(size_t)s * 64 + lane];
    float s0 = sinb[(size_t)s * 64 + lane];
    float c1 = cosb[(size_t)s * 64 + 32 + lane];
    float s1 = sinb[(size_t)s * 64 + 32 + lane];

    if (hh < NH) {
        const float* src = qkvf + (size_t)s * 6144 + hh * 128;
        float x0 = src[lane], x1 = src[32 + lane], x2 = src[64 + lane], x3 = src[96 + lane];
        float v[4];
        v[0] = (x0 * c0 - x1 * s0) * SCALE;
        v[1] = (x1 * c1 + x0 * s1) * SCALE;
        v[2] = x2 * SCALE;
        v[3] = x3 * SCALE;
        size_t base = (size_t)s * 4096 + hh * 128;
        const int off[4] = {0, 32, 64, 96};
#pragma unroll
        for (int i = 0; i < 4; i++) {
            __half h = __float2half_rn(v[i]);
            qh[base + off[i] + lane] = h;
            ql[base + off[i] + lane] = __float2half_rn(v[i] - __half2float(h));
        }
    } else {
        const float* src = qkvf + (size_t)s * 6144 + 4096 + (hh - NH) * 128;
        float x0 = src[lane], x1 = src[32 + lane], x2 = src[64 + lane], x3 = src[96 + lane];
        size_t base = (size_t)s * 1024 + (hh - NH) * 128;
        kh[base + lane]      = __float2half_rn(x0 * c0 - x1 * s0);
        kh[base + 32 + lane] = __float2half_rn(x1 * c1 + x0 * s1);
        kh[base + 64 + lane] = __float2half_rn(x2);
        kh[base + 96 + lane] = __float2half_rn(x3);
    }
}

// ---------------------------------------------------------------------------
// fp16 x2 GEMM: C[M,N] (fp32) = (Ah + Al) * B
// A row-major [M,K] fp16 (hi,lo), B row-major [K,N] fp16.
// CTA 128x256, k-step 32, 8 warps (2m x 4n), warp tile 64x64 (same inner
// loop as the proven R6 kernel), 4-stage cp.async (wait_group 2).
// smem/stage halves: A hi 128x40 (5120) | A lo 5120 | B 32x264 (8448).
// ---------------------------------------------------------------------------
#define PSTG 18688
#define PSMEM (4 * PSTG * 2)

__global__ __launch_bounds__(256, 1)
void hgemm(const __half* __restrict__ Ah, const __half* __restrict__ Al,
           const __half* __restrict__ B, float* __restrict__ C,
           int M, int N, int K, int lda, int ldb, int ldc)
{
    extern __shared__ __half sm[];
    const int bm = blockIdx.y, bn = blockIdx.x;
    const int tid = threadIdx.x, lane = tid & 31, warp = tid >> 5;
    const int wm = warp & 1, wn = warp >> 1;   // wm in {0,1}, wn in {0..3}

    const __half* Agh = Ah + (size_t)bm * 128 * lda;
    const __half* Agl = Al + (size_t)bm * 128 * lda;
    const __half* Bg  = B + bn * 256;

    auto load_stage = [&](int st, int k0) {
        __half* sa = sm + st * PSTG;
        __half* sl = sa + 5120;
        __half* sb = sl + 5120;
#pragma unroll
        for (int i = 0; i < 2; i++) {
            int id = tid + i * 256;
            int r = id >> 2, u = id & 3;
            cp16(smem_u32(sa + r * 40 + u * 8), Agh + (size_t)r * lda + k0 + u * 8);
            cp16(smem_u32(sl + r * 40 + u * 8), Agl + (size_t)r * lda + k0 + u * 8);
        }
#pragma unroll
        for (int i = 0; i < 4; i++) {
            int id = tid + i * 256;
            int r = id >> 5, u = id & 31;
            cp16(smem_u32(sb + r * 264 + u * 8), Bg + (size_t)(k0 + r) * ldb + u * 8);
        }
    };

    float acc[4][8][4];
#pragma unroll
    for (int a = 0; a < 4; a++)
#pragma unroll
        for (int b = 0; b < 8; b++)
#pragma unroll
            for (int c = 0; c < 4; c++) acc[a][b][c] = 0.f;

    const int nk = K >> 5;
    load_stage(0, 0);  CP_COMMIT();
    load_stage(1, 32); CP_COMMIT();
    load_stage(2, 64); CP_COMMIT();
    CP_WAIT(2);
    __syncthreads();

    for (int it = 0; it < nk; it++) {
        const __half* sa = sm + (it & 3) * PSTG;
        const __half* sl = sa + 5120;
        const __half* sb = sl + 5120;
#pragma unroll
        for (int kk = 0; kk < 2; kk++) {
            uint32_t ah[4][4], al[4][4], bb[8][2];
#pragma unroll
            for (int im = 0; im < 4; im++) {
                int r = wm * 64 + im * 16 + (lane & 15);
                int u = kk * 2 + (lane >> 4);
                ldsm4(ah[im], smem_u32(sa + r * 40 + u * 8));
                ldsm4(al[im], smem_u32(sl + r * 40 + u * 8));
            }
#pragma unroll
            for (int jp = 0; jp < 4; jp++) {
                int r = kk * 16 + (lane & 15);
                int u = wn * 8 + jp * 2 + (lane >> 4);
                uint32_t t[4];
                ldsm4t(t, smem_u32(sb + r * 264 + u * 8));
                bb[2 * jp][0] = t[0]; bb[2 * jp][1] = t[1];
                bb[2 * jp + 1][0] = t[2]; bb[2 * jp + 1][1] = t[3];
            }
#pragma unroll
            for (int im = 0; im < 4; im++)
#pragma unroll
                for (int jn = 0; jn < 8; jn++) {
                    mma_f16(acc[im][jn], ah[im], bb[jn]);
                    mma_f16(acc[im][jn], al[im], bb[jn]);
                }
        }
        int nx = it + 3;
        if (nx < nk) load_stage(nx & 3, nx * 32);
        CP_COMMIT();
        CP_WAIT(2);
        __syncthreads();
    }

    const int gid = lane >> 2, tig = lane & 3;
#pragma unroll
    for (int im = 0; im < 4; im++) {
        int row = bm * 128 + wm * 64 + im * 16 + gid;
#pragma unroll
        for (int jn = 0; jn < 8; jn++) {
            int col = bn * 256 + wn * 64 + jn * 8 + tig * 2;
            *(float2*)&C[(size_t)row * ldc + col] = make_float2(acc[im][jn][0], acc[im][jn][1]);
            *(float2*)&C[(size_t)(row + 8) * ldc + col] = make_float2(acc[im][jn][2], acc[im][jn][3]);
        }
    }
}

// ---------------------------------------------------------------------------
// Flash attention (unchanged, known good from R6)
// ---------------------------------------------------------------------------
#define FSMEM ((2 * 128 * 136 + 6 * 64 * 136) * 2)

__global__ __launch_bounds__(256, 1)
void flash_kernel(const __half* __restrict__ qh, const __half* __restrict__ ql,
                  const __half* __restrict__ kh,
                  const __half* __restrict__ vh, const __half* __restrict__ vl,
                  const float* __restrict__ sinks,
                  __half* __restrict__ ath, __half* __restrict__ atl)
{
    extern __shared__ __half sm[];
    __half* Qh = sm;
    __half* Ql = Qh + 128 * 136;
    __half* Ks = Ql + 128 * 136;
    __half* Vs = Ks + 2 * 64 * 136;
    __half* Vx = Vs + 2 * 64 * 136;

    const int qt = gridDim.x - 1 - blockIdx.x;
    const int h = blockIdx.y, kvh = h >> 2;
    const int tid = threadIdx.x, lane = tid & 31, w = tid >> 5;
    const int gid = lane >> 2, tig = lane & 3;

    {
        const __half* src = qh + (size_t)(qt * 128) * 4096 + h * 128;
        const __half* srl = ql + (size_t)(qt * 128) * 4096 + h * 128;
#pragma unroll
        for (int i = 0; i < 8; i++) {
            int id = tid + i * 256;
            int r = id >> 4, u = id & 15;
            cp16(smem_u32(Qh + r * 136 + u * 8), src + (size_t)r * 4096 + u * 8);
            cp16(smem_u32(Ql + r * 136 + u * 8), srl + (size_t)r * 4096 + u * 8);
        }
    }
    auto loadKV = [&](int kt) {
        int buf = (kt & 1) * 64 * 136;
        const __half* ks = kh + (size_t)(kt * 64) * 1024 + kvh * 128;
        const __half* vs = vh + (size_t)(kt * 64) * 1024 + kvh * 128;
        const __half* vx = vl + (size_t)(kt * 64) * 1024 + kvh * 128;
#pragma unroll
        for (int i = 0; i < 4; i++) {
            int id = tid + i * 256;
            int r = id >> 4, u = id & 15;
            cp16(smem_u32(Ks + buf + r * 136 + u * 8), ks + (size_t)r * 1024 + u * 8);
            cp16(smem_u32(Vs + buf + r * 136 + u * 8), vs + (size_t)r * 1024 + u * 8);
            cp16(smem_u32(Vx + buf + r * 136 + u * 8), vx + (size_t)r * 1024 + u * 8);
        }
    };

    loadKV(0);
    CP_COMMIT();

    float m0 = -1e30f, m1 = -1e30f, l0 = 0.f, l1 = 0.f;
    float O[16][4];
#pragma unroll
    for (int i = 0; i < 16; i++)
#pragma unroll
        for (int j = 0; j < 4; j++) O[i][j] = 0.f;

    const int nkt = 2 * (qt + 1);
    const int rowg0 = qt * 128 + w * 16 + gid;

    for (int kt = 0; kt < nkt; kt++) {
        CP_WAIT(0);
        __syncthreads();
        if (kt + 1 < nkt) loadKV(kt + 1);
        CP_COMMIT();

        const __half* Kb  = Ks + (kt & 1) * 64 * 136;
        const __half* Vbh = Vs + (kt & 1) * 64 * 136;
        const __half* Vbl = Vx + (kt & 1) * 64 * 136;

        float S[8][4];
#pragma unroll
        for (int i = 0; i < 8; i++)
#pragma unroll
            for (int j = 0; j < 4; j++) S[i][j] = 0.f;
#pragma unroll
        for (int kk = 0; kk < 8; kk++) {
            uint32_t qa[4], qb[4], kb[8][2];
            {
                int r = w * 16 + (lane & 15);
                int u = kk * 2 + (lane >> 4);
                ldsm4(qa, smem_u32(Qh + r * 136 + u * 8));
                ldsm4(qb, smem_u32(Ql + r * 136 + u * 8));
            }
#pragma unroll
            for (int jp = 0; jp < 4; jp++) {
                int r = jp * 16 + (lane & 15);
                int u = kk * 2 + (lane >> 4);
                uint32_t t[4];
                ldsm4(t, smem_u32(Kb + r * 136 + u * 8));
                kb[2 * jp][0] = t[0]; kb[2 * jp][1] = t[2];
                kb[2 * jp + 1][0] = t[1]; kb[2 * jp + 1][1] = t[3];
            }
#pragma unroll
            for (int jn = 0; jn < 8; jn++) {
                mma_f16(S[jn], qa, kb[jn]);
                mma_f16(S[jn], qb, kb[jn]);
            }
        }

        if (kt * 64 + 63 > qt * 128 + w * 16) {
#pragma unroll
            for (int jn = 0; jn < 8; jn++) {
                int colb = kt * 64 + jn * 8 + tig * 2;
                if (colb > rowg0)         S[jn][0] = -1e30f;
                if (colb + 1 > rowg0)     S[jn][1] = -1e30f;
                if (colb > rowg0 + 8)     S[jn][2] = -1e30f;
                if (colb + 1 > rowg0 + 8) S[jn][3] = -1e30f;
            }
        }

        float mr0 = -1e30f, mr1 = -1e30f;
#pragma unroll
        for (int jn = 0; jn < 8; jn++) {
            mr0 = fmaxf(mr0, fmaxf(S[jn][0], S[jn][1]));
            mr1 = fmaxf(mr1, fmaxf(S[jn][2], S[jn][3]));
        }
        mr0 = fmaxf(mr0, __shfl_xor_sync(0xffffffff, mr0, 1));
        mr0 = fmaxf(mr0, __shfl_xor_sync(0xffffffff, mr0, 2));
        mr1 = fmaxf(mr1, __shfl_xor_sync(0xffffffff, mr1, 1));
        mr1 = fmaxf(mr1, __shfl_xor_sync(0xffffffff, mr1, 2));
        float mn0 = fmaxf(m0, mr0), mn1 = fmaxf(m1, mr1);
        float a0 = __expf(m0 - mn0), a1 = __expf(m1 - mn1);

        float sum0 = 0.f, sum1 = 0.f;
        uint32_t ph[4][4], pl[4][4];
#pragma unroll
        for (int j = 0; j < 4; j++) {
#pragma unroll
            for (int t = 0; t < 2; t++) {
                float p0 = __expf(S[2 * j + t][0] - mn0);
                float p1 = __expf(S[2 * j + t][1] - mn0);
                float p2 = __expf(S[2 * j + t][2] - mn1);
                float p3 = __expf(S[2 * j + t][3] - mn1);
                sum0 += p0 + p1;
                sum1 += p2 + p3;
                __half h0 = __float2half_rn(p0), h1 = __float2half_rn(p1);
                __half h2 = __float2half_rn(p2), h3 = __float2half_rn(p3);
                __half2 u01; u01.x = h0; u01.y = h1;
                __half2 u23; u23.x = h2; u23.y = h3;
                ph[j][2 * t + 0] = *(uint32_t*)&u01;
                ph[j][2 * t + 1] = *(uint32_t*)&u23;
                pl[j][2 * t + 0] = pack_h2(p0 - __half2float(h0), p1 - __half2float(h1));
                pl[j][2 * t + 1] = pack_h2(p2 - __half2float(h2), p3 - __half2float(h3));
            }
        }
        sum0 += __shfl_xor_sync(0xffffffff, sum0, 1);
        sum0 += __shfl_xor_sync(0xffffffff, sum0, 2);
        sum1 += __shfl_xor_sync(0xffffffff, sum1, 1);
        sum1 += __shfl_xor_sync(0xffffffff, sum1, 2);
        l0 = l0 * a0 + sum0;
        l1 = l1 * a1 + sum1;
        m0 = mn0; m1 = mn1;
#pragma unroll
        for (int nt = 0; nt < 16; nt++) {
            O[nt][0] *= a0; O[nt][1] *= a0;
            O[nt][2] *= a1; O[nt][3] *= a1;
        }

#pragma unroll
        for (int ks = 0; ks < 4; ks++) {
            uint32_t vb[16][2];
#pragma unroll
            for (int jp = 0; jp < 8; jp++) {
                int r = ks * 16 + (lane & 15);
                int u = jp * 2 + (lane >> 4);
                uint32_t t[4];
                ldsm4t(t, smem_u32(Vbh + r * 136 + u * 8));
                vb[2 * jp][0] = t[0]; vb[2 * jp][1] = t[1];
                vb[2 * jp + 1][0] = t[2]; vb[2 * jp + 1][1] = t[3];
            }
#pragma unroll
            for (int nt = 0; nt < 16; nt++) {
                mma_f16(O[nt], ph[ks], vb[nt]);
                mma_f16(O[nt], pl[ks], vb[nt]);
            }
#pragma unroll
            for (int jp = 0; jp < 8; jp++) {
                int r = ks * 16 + (lane & 15);
                int u = jp * 2 + (lane >> 4);
                uint32_t t[4];
                ldsm4t(t, smem_u32(Vbl + r * 136 + u * 8));
                vb[2 * jp][0] = t[0]; vb[2 * jp][1] = t[1];
                vb[2 * jp + 1][0] = t[2]; vb[2 * jp + 1][1] = t[3];
            }
#pragma unroll
            for (int nt = 0; nt < 16; nt++) {
                mma_f16(O[nt], ph[ks], vb[nt]);
            }
        }
    }

    float sink = sinks[h];
    l0 += __expf(sink - m0);
    l1 += __expf(sink - m1);
    float i0 = 1.f / l0, i1 = 1.f / l1;
    int row0 = qt * 128 + w * 16 + gid;
#pragma unroll
    for (int nt = 0; nt < 16; nt++) {
        int col = h * 128 + nt * 8 + tig * 2;
        float f0 = O[nt][0] * i0, f1 = O[nt][1] * i0;
        float f2 = O[nt][2] * i1, f3 = O[nt][3] * i1;
        __half h0 = __float2half_rn(f0), h1 = __float2half_rn(f1);
        __half h2 = __float2half_rn(f2), h3 = __float2half_rn(f3);
        __half2 u01; u01.x = h0; u01.y = h1;
        __half2 u23; u23.x = h2; u23.y = h3;
        *(__half2*)&ath[(size_t)row0 * 4096 + col] = u01;
        *(__half2*)&ath[(size_t)(row0 + 8) * 4096 + col] = u23;
        *(uint32_t*)&atl[(size_t)row0 * 4096 + col] =
            pack_h2(f0 - __half2float(h0), f1 - __half2float(h1));
        *(uint32_t*)&atl[(size_t)(row0 + 8) * 4096 + col] =
            pack_h2(f2 - __half2float(h2), f3 - __half2float(h3));
    }
}

// ---------------------------------------------------------------------------
extern "C" void kernel_launch(void* const* d_in, const int* in_sizes, int n_in,
                              void* d_out, int out_size)
{
    const float* X_in  = (const float*)d_in[0];
    const float* cosb  = (const float*)d_in[1];
    const float* sinb  = (const float*)d_in[2];
    const float* Wq_in = (const float*)d_in[4];
    const float* Wk_in = (const float*)d_in[5];
    const float* Wv_in = (const float*)d_in[6];
    const float* Wo_in = (const float*)d_in[7];
    const float* sinks = (const float*)d_in[8];
    float* out = (float*)d_out;

    __half *Xh, *Xl, *Wqkv, *Woh, *qh, *ql, *kh, *vh, *vl, *ath, *atl;
    float *qkvf;
    cudaGetSymbolAddress((void**)&Xh,   g_Xh);
    cudaGetSymbolAddress((void**)&Xl,   g_Xl);
    cudaGetSymbolAddress((void**)&Wqkv, g_Wqkv);
    cudaGetSymbolAddress((void**)&Woh,  g_Woh);
    cudaGetSymbolAddress((void**)&qkvf, g_qkvf);
    cudaGetSymbolAddress((void**)&qh,   g_qh);
    cudaGetSymbolAddress((void**)&ql,   g_ql);
    cudaGetSymbolAddress((void**)&kh,   g_kh);
    cudaGetSymbolAddress((void**)&vh,   g_vh);
    cudaGetSymbolAddress((void**)&vl,   g_vl);
    cudaGetSymbolAddress((void**)&ath,  g_ath);
    cudaGetSymbolAddress((void**)&atl,  g_atl);

    cudaFuncSetAttribute((const void*)hgemm, cudaFuncAttributeMaxDynamicSharedMemorySize, PSMEM);
    cudaFuncSetAttribute((const void*)flash_kernel, cudaFuncAttributeMaxDynamicSharedMemorySize, FSMEM);

    // 0. prep
    split2_kernel<<<2048, 256>>>(X_in, Xh, Xl, SEQ * HID);
    wqkv_pack<<<8192, 256>>>(Wq_in, Wk_in, Wv_in, Wqkv);
    split1_kernel<<<4096, 256>>>(Wo_in, Woh, 4096 * HID);

    // 1. fused QKV projection: qkvf = (Xh+Xl) @ Wqkv
    hgemm<<<dim3(6144 / 256, SEQ / 128), 256, PSMEM>>>(Xh, Xl, Wqkv, qkvf,
                                                       SEQ, 6144, HID, HID, 6144, 6144);

    // 2. RoPE + splits
    rope_split_kernel<<<SEQ * 40 / 8, 256>>>(qkvf, cosb, sinb, qh, ql, kh);
    vsplit_kernel<<<1024, 256>>>(qkvf, vh, vl);

    // 3. flash attention
    flash_kernel<<<dim3(16, 32), 256, FSMEM>>>(qh, ql, kh, vh, vl, sinks, ath, atl);

    // 4. output projection: out = (ath+atl) @ Woh
    hgemm<<<dim3(4096 / 256, SEQ / 128), 256, PSMEM>>>(ath, atl, Woh, out,
                                                       SEQ, HID, 4096, 4096, HID, HID);
}

// round 11
// speedup vs baseline: 1.1946x; 1.1946x over previous
#include <cuda_runtime.h>
#include <cuda_fp16.h>
#include <cstdint>

#define SEQ 2048
#define HID 4096
#define NH  32
#define NKV 8
#define HD  128
#define SCALE 0.08838834764831845f

// ---------------- scratch (device globals; no allocations) ----------------
__device__ __half g_Xh  [(size_t)SEQ * HID];
__device__ __half g_Wqkv[(size_t)HID * 6144];   // [Wq | Wk | Wv] fp16 [K,N]
__device__ __half g_Woh [(size_t)4096 * HID];   // Wo fp16 [K,N]
__device__ float  g_qkvf[(size_t)SEQ * 6144];
__device__ __half g_qh  [(size_t)SEQ * 4096];
__device__ __half g_ql  [(size_t)SEQ * 4096];
__device__ __half g_kh  [(size_t)SEQ * 1024];
__device__ __half g_vh  [(size_t)SEQ * 1024];
__device__ __half g_vl  [(size_t)SEQ * 1024];
__device__ __half g_ath [(size_t)SEQ * 4096];
__device__ __half g_atl [(size_t)SEQ * 4096];

// ---------------- helpers ----------------
__device__ __forceinline__ uint32_t smem_u32(const void* p) {
    return (uint32_t)__cvta_generic_to_shared(p);
}
__device__ __forceinline__ void cp16(uint32_t s, const void* g) {
    asm volatile("cp.async.cg.shared.global [%0], [%1], 16;\n" :: "r"(s), "l"(g));
}
#define CP_COMMIT() asm volatile("cp.async.commit_group;")
#define CP_WAIT(n)  asm volatile("cp.async.wait_group %0;" :: "n"(n))

__device__ __forceinline__ void ldsm4(uint32_t* r, uint32_t a) {
    asm volatile("ldmatrix.sync.aligned.m8n8.x4.shared.b16 {%0,%1,%2,%3}, [%4];"
                 : "=r"(r[0]), "=r"(r[1]), "=r"(r[2]), "=r"(r[3]) : "r"(a));
}
__device__ __forceinline__ void ldsm4t(uint32_t* r, uint32_t a) {
    asm volatile("ldmatrix.sync.aligned.m8n8.x4.trans.shared.b16 {%0,%1,%2,%3}, [%4];"
                 : "=r"(r[0]), "=r"(r[1]), "=r"(r[2]), "=r"(r[3]) : "r"(a));
}
__device__ __forceinline__ void mma_f16(float* c, const uint32_t* a, const uint32_t* b) {
    asm volatile("mma.sync.aligned.m16n8k16.row.col.f32.f16.f16.f32 "
                 "{%0,%1,%2,%3},{%4,%5,%6,%7},{%8,%9},{%0,%1,%2,%3};"
                 : "+f"(c[0]), "+f"(c[1]), "+f"(c[2]), "+f"(c[3])
                 : "r"(a[0]), "r"(a[1]), "r"(a[2]), "r"(a[3]), "r"(b[0]), "r"(b[1]));
}
__device__ __forceinline__ uint32_t pack_h2(float a, float b) {
    __half2 t = __floats2half2_rn(a, b);
    return *reinterpret_cast<uint32_t*>(&t);
}

// ---------------- prep kernels ----------------
__global__ void split1_kernel(const float* __restrict__ s, __half* __restrict__ d, int n) {
    for (int i = blockIdx.x * blockDim.x + threadIdx.x; i < n; i += gridDim.x * blockDim.x)
        d[i] = __float2half_rn(s[i]);
}
__global__ void wqkv_pack(const float* __restrict__ Wq, const float* __restrict__ Wk,
                          const float* __restrict__ Wv, __half* __restrict__ d) {
    const int n = HID * 6144;
    for (int i = blockIdx.x * blockDim.x + threadIdx.x; i < n; i += gridDim.x * blockDim.x) {
        int r = i / 6144, c = i - r * 6144;
        float x;
        if (c < 4096)      x = Wq[(size_t)r * 4096 + c];
        else if (c < 5120) x = Wk[(size_t)r * 1024 + (c - 4096)];
        else               x = Wv[(size_t)r * 1024 + (c - 5120)];
        d[i] = __float2half_rn(x);
    }
}
__global__ void vsplit_kernel(const float* __restrict__ qkvf, __half* __restrict__ vh,
                              __half* __restrict__ vl) {
    int n = SEQ * 1024;
    for (int i = blockIdx.x * blockDim.x + threadIdx.x; i < n; i += gridDim.x * blockDim.x) {
        int r = i >> 10, c = i & 1023;
        float x = qkvf[(size_t)r * 6144 + 5120 + c];
        __half hh = __float2half_rn(x);
        vh[i] = hh;
        vl[i] = __float2half_rn(x - __half2float(hh));
    }
}
__global__ void rope_split_kernel(const float* __restrict__ qkvf,
                                  const float* __restrict__ cosb, const float* __restrict__ sinb,
                                  __half* __restrict__ qh, __half* __restrict__ ql,
                                  __half* __restrict__ kh)
{
    int gw = blockIdx.x * 8 + (threadIdx.x >> 5);
    int lane = threadIdx.x & 31;
    int s = gw / 40, hh = gw % 40;
    if (s >= SEQ) return;

    float c0 = cosb[(size_t)s * 64 + lane];
    float s0 = sinb[(size_t)s * 64 + lane];
    float c1 = cosb[(size_t)s * 64 + 32 + lane];
    float s1 = sinb[(size_t)s * 64 + 32 + lane];

    if (hh < NH) {
        const float* src = qkvf + (size_t)s * 6144 + hh * 128;
        float x0 = src[lane], x1 = src[32 + lane], x2 = src[64 + lane], x3 = src[96 + lane];
        float v[4];
        v[0] = (x0 * c0 - x1 * s0) * SCALE;
        v[1] = (x1 * c1 + x0 * s1) * SCALE;
        v[2] = x2 * SCALE;
        v[3] = x3 * SCALE;
        size_t base = (size_t)s * 4096 + hh * 128;
        const int off[4] = {0, 32, 64, 96};
#pragma unroll
        for (int i = 0; i < 4; i++) {
            __half h = __float2half_rn(v[i]);
            qh[base + off[i] + lane] = h;
            ql[base + off[i] + lane] = __float2half_rn(v[i] - __half2float(h));
        }
    } else {
        const float* src = qkvf + (size_t)s * 6144 + 4096 + (hh - NH) * 128;
        float x0 = src[lane], x1 = src[32 + lane], x2 = src[64 + lane], x3 = src[96 + lane];
        size_t base = (size_t)s * 1024 + (hh - NH) * 128;
        kh[base + lane]      = __float2half_rn(x0 * c0 - x1 * s0);
        kh[base + 32 + lane] = __float2half_rn(x1 * c1 + x0 * s1);
        kh[base + 64 + lane] = __float2half_rn(x2);
        kh[base + 96 + lane] = __float2half_rn(x3);
    }
}

// ---------------------------------------------------------------------------
// hgemm1: C[M,N](fp32) = Ah * B  (single-A fp16 chain)
// CTA 128x128 k32, 4 warps (2x2, warp 64x64), 3-stage cp.async, loads at top.
// stage halves: Ah 128x40 (5120) | B 32x136 (4352) = 9472
// ---------------------------------------------------------------------------
#define PSTG1 9472
#define PSMEM1 (3 * PSTG1 * 2)

__global__ __launch_bounds__(128, 3)
void hgemm1(const __half* __restrict__ Ah, const __half* __restrict__ B,
            float* __restrict__ C, int M, int N, int K, int lda, int ldb, int ldc)
{
    extern __shared__ __half sm[];
    const int bm = blockIdx.y, bn = blockIdx.x;
    const int tid = threadIdx.x, lane = tid & 31, warp = tid >> 5;
    const int wm = warp & 1, wn = warp >> 1;

    const __half* Agh = Ah + (size_t)bm * 128 * lda;
    const __half* Bg  = B + bn * 128;

    auto load_stage = [&](int st, int k0) {
        __half* sa = sm + st * PSTG1;
        __half* sb = sa + 5120;
#pragma unroll
        for (int i = 0; i < 4; i++) {
            int id = tid + i * 128;
            int r = id >> 2, u = id & 3;
            cp16(smem_u32(sa + r * 40 + u * 8), Agh + (size_t)r * lda + k0 + u * 8);
        }
#pragma unroll
        for (int i = 0; i < 4; i++) {
            int id = tid + i * 128;
            int r = id >> 4, u = id & 15;
            cp16(smem_u32(sb + r * 136 + u * 8), Bg + (size_t)(k0 + r) * ldb + u * 8);
        }
    };

    float acc[4][8][4];
#pragma unroll
    for (int a = 0; a < 4; a++)
#pragma unroll
        for (int b = 0; b < 8; b++)
#pragma unroll
            for (int c = 0; c < 4; c++) acc[a][b][c] = 0.f;

    const int nk = K >> 5;
    load_stage(0, 0);  CP_COMMIT();
    load_stage(1, 32); CP_COMMIT();
    CP_WAIT(1);
    __syncthreads();

    for (int it = 0; it < nk; it++) {
        int cur = it % 3;
        int nx = it + 2;
        if (nx < nk) load_stage(nx % 3, nx * 32);
        CP_COMMIT();

        const __half* sa = sm + cur * PSTG1;
        const __half* sb = sa + 5120;
#pragma unroll
        for (int kk = 0; kk < 2; kk++) {
            uint32_t ah[4][4], bb[8][2];
#pragma unroll
            for (int im = 0; im < 4; im++) {
                int r = wm * 64 + im * 16 + (lane & 15);
                int u = kk * 2 + (lane >> 4);
                ldsm4(ah[im], smem_u32(sa + r * 40 + u * 8));
            }
#pragma unroll
            for (int jp = 0; jp < 4; jp++) {
                int r = kk * 16 + (lane & 15);
                int u = wn * 8 + jp * 2 + (lane >> 4);
                uint32_t t[4];
                ldsm4t(t, smem_u32(sb + r * 136 + u * 8));
                bb[2 * jp][0] = t[0]; bb[2 * jp][1] = t[1];
                bb[2 * jp + 1][0] = t[2]; bb[2 * jp + 1][1] = t[3];
            }
#pragma unroll
            for (int im = 0; im < 4; im++)
#pragma unroll
                for (int jn = 0; jn < 8; jn++)
                    mma_f16(acc[im][jn], ah[im], bb[jn]);
        }
        CP_WAIT(1);
        __syncthreads();
    }

    const int gid = lane >> 2, tig = lane & 3;
#pragma unroll
    for (int im = 0; im < 4; im++) {
        int row = bm * 128 + wm * 64 + im * 16 + gid;
#pragma unroll
        for (int jn = 0; jn < 8; jn++) {
            int col = bn * 128 + wn * 64 + jn * 8 + tig * 2;
            *(float2*)&C[(size_t)row * ldc + col] = make_float2(acc[im][jn][0], acc[im][jn][1]);
            *(float2*)&C[(size_t)(row + 8) * ldc + col] = make_float2(acc[im][jn][2], acc[im][jn][3]);
        }
    }
}

// ---------------------------------------------------------------------------
// hgemm2: C[M,N](fp32) = (Ah + Al) * B  (dual-A chains; exact R6 kernel)
// stage halves: Ah 5120 | Al 5120 | B 4352 = 14592
// ---------------------------------------------------------------------------
#define PSTG2 14592
#define PSMEM2 (3 * PSTG2 * 2)

__global__ __launch_bounds__(128, 2)
void hgemm2(const __half* __restrict__ Ah, const __half* __restrict__ Al,
            const __half* __restrict__ B, float* __restrict__ C,
            int M, int N, int K, int lda, int ldb, int ldc)
{
    extern __shared__ __half sm[];
    const int bm = blockIdx.y, bn = blockIdx.x;
    const int tid = threadIdx.x, lane = tid & 31, warp = tid >> 5;
    const int wm = warp & 1, wn = warp >> 1;

    const __half* Agh = Ah + (size_t)bm * 128 * lda;
    const __half* Agl = Al + (size_t)bm * 128 * lda;
    const __half* Bg  = B + bn * 128;

    auto load_stage = [&](int st, int k0) {
        __half* sa = sm + st * PSTG2;
        __half* sl = sa + 5120;
        __half* sb = sl + 5120;
#pragma unroll
        for (int i = 0; i < 4; i++) {
            int id = tid + i * 128;
            int r = id >> 2, u = id & 3;
            cp16(smem_u32(sa + r * 40 + u * 8), Agh + (size_t)r * lda + k0 + u * 8);
            cp16(smem_u32(sl + r * 40 + u * 8), Agl + (size_t)r * lda + k0 + u * 8);
        }
#pragma unroll
        for (int i = 0; i < 4; i++) {
            int id = tid + i * 128;
            int r = id >> 4, u = id & 15;
            cp16(smem_u32(sb + r * 136 + u * 8), Bg + (size_t)(k0 + r) * ldb + u * 8);
        }
    };

    float acc[4][8][4];
#pragma unroll
    for (int a = 0; a < 4; a++)
#pragma unroll
        for (int b = 0; b < 8; b++)
#pragma unroll
            for (int c = 0; c < 4; c++) acc[a][b][c] = 0.f;

    const int nk = K >> 5;
    load_stage(0, 0);  CP_COMMIT();
    load_stage(1, 32); CP_COMMIT();
    CP_WAIT(1);
    __syncthreads();

    for (int it = 0; it < nk; it++) {
        int cur = it % 3;
        int nx = it + 2;
        if (nx < nk) load_stage(nx % 3, nx * 32);
        CP_COMMIT();

        const __half* sa = sm + cur * PSTG2;
        const __half* sl = sa + 5120;
        const __half* sb = sl + 5120;
#pragma unroll
        for (int kk = 0; kk < 2; kk++) {
            uint32_t ah[4][4], al[4][4], bb[8][2];
#pragma unroll
            for (int im = 0; im < 4; im++) {
                int r = wm * 64 + im * 16 + (lane & 15);
                int u = kk * 2 + (lane >> 4);
                ldsm4(ah[im], smem_u32(sa + r * 40 + u * 8));
                ldsm4(al[im], smem_u32(sl + r * 40 + u * 8));
            }
#pragma unroll
            for (int jp = 0; jp < 4; jp++) {
                int r = kk * 16 + (lane & 15);
                int u = wn * 8 + jp * 2 + (lane >> 4);
                uint32_t t[4];
                ldsm4t(t, smem_u32(sb + r * 136 + u * 8));
                bb[2 * jp][0] = t[0]; bb[2 * jp][1] = t[1];
                bb[2 * jp + 1][0] = t[2]; bb[2 * jp + 1][1] = t[3];
            }
#pragma unroll
            for (int im = 0; im < 4; im++)
#pragma unroll
                for (int jn = 0; jn < 8; jn++) {
                    mma_f16(acc[im][jn], ah[im], bb[jn]);
                    mma_f16(acc[im][jn], al[im], bb[jn]);
                }
        }
        CP_WAIT(1);
        __syncthreads();
    }

    const int gid = lane >> 2, tig = lane & 3;
#pragma unroll
    for (int im = 0; im < 4; im++) {
        int row = bm * 128 + wm * 64 + im * 16 + gid;
#pragma unroll
        for (int jn = 0; jn < 8; jn++) {
            int col = bn * 128 + wn * 64 + jn * 8 + tig * 2;
            *(float2*)&C[(size_t)row * ldc + col] = make_float2(acc[im][jn][0], acc[im][jn][1]);
            *(float2*)&C[(size_t)(row + 8) * ldc + col] = make_float2(acc[im][jn][2], acc[im][jn][3]);
        }
    }
}

// ---------------------------------------------------------------------------
// Flash attention (unchanged, known good from R6)
// ---------------------------------------------------------------------------
#define FSMEM ((2 * 128 * 136 + 6 * 64 * 136) * 2)

__global__ __launch_bounds__(256, 1)
void flash_kernel(const __half* __restrict__ qh, const __half* __restrict__ ql,
                  const __half* __restrict__ kh,
                  const __half* __restrict__ vh, const __half* __restrict__ vl,
                  const float* __restrict__ sinks,
                  __half* __restrict__ ath, __half* __restrict__ atl)
{
    extern __shared__ __half sm[];
    __half* Qh = sm;
    __half* Ql = Qh + 128 * 136;
    __half* Ks = Ql + 128 * 136;
    __half* Vs = Ks + 2 * 64 * 136;
    __half* Vx = Vs + 2 * 64 * 136;

    const int qt = gridDim.x - 1 - blockIdx.x;
    const int h = blockIdx.y, kvh = h >> 2;
    const int tid = threadIdx.x, lane = tid & 31, w = tid >> 5;
    const int gid = lane >> 2, tig = lane & 3;

    {
        const __half* src = qh + (size_t)(qt * 128) * 4096 + h * 128;
        const __half* srl = ql + (size_t)(qt * 128) * 4096 + h * 128;
#pragma unroll
        for (int i = 0; i < 8; i++) {
            int id = tid + i * 256;
            int r = id >> 4, u = id & 15;
            cp16(smem_u32(Qh + r * 136 + u * 8), src + (size_t)r * 4096 + u * 8);
            cp16(smem_u32(Ql + r * 136 + u * 8), srl + (size_t)r * 4096 + u * 8);
        }
    }
    auto loadKV = [&](int kt) {
        int buf = (kt & 1) * 64 * 136;
        const __half* ks = kh + (size_t)(kt * 64) * 1024 + kvh * 128;
        const __half* vs = vh + (size_t)(kt * 64) * 1024 + kvh * 128;
        const __half* vx = vl + (size_t)(kt * 64) * 1024 + kvh * 128;
#pragma unroll
        for (int i = 0; i < 4; i++) {
            int id = tid + i * 256;
            int r = id >> 4, u = id & 15;
            cp16(smem_u32(Ks + buf + r * 136 + u * 8), ks + (size_t)r * 1024 + u * 8);
            cp16(smem_u32(Vs + buf + r * 136 + u * 8), vs + (size_t)r * 1024 + u * 8);
            cp16(smem_u32(Vx + buf + r * 136 + u * 8), vx + (size_t)r * 1024 + u * 8);
        }
    };

    loadKV(0);
    CP_COMMIT();

    float m0 = -1e30f, m1 = -1e30f, l0 = 0.f, l1 = 0.f;
    float O[16][4];
#pragma unroll
    for (int i = 0; i < 16; i++)
#pragma unroll
        for (int j = 0; j < 4; j++) O[i][j] = 0.f;

    const int nkt = 2 * (qt + 1);
    const int rowg0 = qt * 128 + w * 16 + gid;

    for (int kt = 0; kt < nkt; kt++) {
        CP_WAIT(0);
        __syncthreads();
        if (kt + 1 < nkt) loadKV(kt + 1);
        CP_COMMIT();

        const __half* Kb  = Ks + (kt & 1) * 64 * 136;
        const __half* Vbh = Vs + (kt & 1) * 64 * 136;
        const __half* Vbl = Vx + (kt & 1) * 64 * 136;

        float S[8][4];
#pragma unroll
        for (int i = 0; i < 8; i++)
#pragma unroll
            for (int j = 0; j < 4; j++) S[i][j] = 0.f;
#pragma unroll
        for (int kk = 0; kk < 8; kk++) {
            uint32_t qa[4], qb[4], kb[8][2];
            {
                int r = w * 16 + (lane & 15);
                int u = kk * 2 + (lane >> 4);
                ldsm4(qa, smem_u32(Qh + r * 136 + u * 8));
                ldsm4(qb, smem_u32(Ql + r * 136 + u * 8));
            }
#pragma unroll
            for (int jp = 0; jp < 4; jp++) {
                int r = jp * 16 + (lane & 15);
                int u = kk * 2 + (lane >> 4);
                uint32_t t[4];
                ldsm4(t, smem_u32(Kb + r * 136 + u * 8));
                kb[2 * jp][0] = t[0]; kb[2 * jp][1] = t[2];
                kb[2 * jp + 1][0] = t[1]; kb[2 * jp + 1][1] = t[3];
            }
#pragma unroll
            for (int jn = 0; jn < 8; jn++) {
                mma_f16(S[jn], qa, kb[jn]);
                mma_f16(S[jn], qb, kb[jn]);
            }
        }

        if (kt * 64 + 63 > qt * 128 + w * 16) {
#pragma unroll
            for (int jn = 0; jn < 8; jn++) {
                int colb = kt * 64 + jn * 8 + tig * 2;
                if (colb > rowg0)         S[jn][0] = -1e30f;
                if (colb + 1 > rowg0)     S[jn][1] = -1e30f;
                if (colb > rowg0 + 8)     S[jn][2] = -1e30f;
                if (colb + 1 > rowg0 + 8) S[jn][3] = -1e30f;
            }
        }

        float mr0 = -1e30f, mr1 = -1e30f;
#pragma unroll
        for (int jn = 0; jn < 8; jn++) {
            mr0 = fmaxf(mr0, fmaxf(S[jn][0], S[jn][1]));
            mr1 = fmaxf(mr1, fmaxf(S[jn][2], S[jn][3]));
        }
        mr0 = fmaxf(mr0, __shfl_xor_sync(0xffffffff, mr0, 1));
        mr0 = fmaxf(mr0, __shfl_xor_sync(0xffffffff, mr0, 2));
        mr1 = fmaxf(mr1, __shfl_xor_sync(0xffffffff, mr1, 1));
        mr1 = fmaxf(mr1, __shfl_xor_sync(0xffffffff, mr1, 2));
        float mn0 = fmaxf(m0, mr0), mn1 = fmaxf(m1, mr1);
        float a0 = __expf(m0 - mn0), a1 = __expf(m1 - mn1);

        float sum0 = 0.f, sum1 = 0.f;
        uint32_t ph[4][4], pl[4][4];
#pragma unroll
        for (int j = 0; j < 4; j++) {
#pragma unroll
            for (int t = 0; t < 2; t++) {
                float p0 = __expf(S[2 * j + t][0] - mn0);
                float p1 = __expf(S[2 * j + t][1] - mn0);
                float p2 = __expf(S[2 * j + t][2] - mn1);
                float p3 = __expf(S[2 * j + t][3] - mn1);
                sum0 += p0 + p1;
                sum1 += p2 + p3;
                __half h0 = __float2half_rn(p0), h1 = __float2half_rn(p1);
                __half h2 = __float2half_rn(p2), h3 = __float2half_rn(p3);
                __half2 u01; u01.x = h0; u01.y = h1;
                __half2 u23; u23.x = h2; u23.y = h3;
                ph[j][2 * t + 0] = *(uint32_t*)&u01;
                ph[j][2 * t + 1] = *(uint32_t*)&u23;
                pl[j][2 * t + 0] = pack_h2(p0 - __half2float(h0), p1 - __half2float(h1));
                pl[j][2 * t + 1] = pack_h2(p2 - __half2float(h2), p3 - __half2float(h3));
            }
        }
        sum0 += __shfl_xor_sync(0xffffffff, sum0, 1);
        sum0 += __shfl_xor_sync(0xffffffff, sum0, 2);
        sum1 += __shfl_xor_sync(0xffffffff, sum1, 1);
        sum1 += __shfl_xor_sync(0xffffffff, sum1, 2);
        l0 = l0 * a0 + sum0;
        l1 = l1 * a1 + sum1;
        m0 = mn0; m1 = mn1;
#pragma unroll
        for (int nt = 0; nt < 16; nt++) {
            O[nt][0] *= a0; O[nt][1] *= a0;
            O[nt][2] *= a1; O[nt][3] *= a1;
        }

#pragma unroll
        for (int ks = 0; ks < 4; ks++) {
            uint32_t vb[16][2];
#pragma unroll
            for (int jp = 0; jp < 8; jp++) {
                int r = ks * 16 + (lane & 15);
                int u = jp * 2 + (lane >> 4);
                uint32_t t[4];
                ldsm4t(t, smem_u32(Vbh + r * 136 + u * 8));
                vb[2 * jp][0] = t[0]; vb[2 * jp][1] = t[1];
                vb[2 * jp + 1][0] = t[2]; vb[2 * jp + 1][1] = t[3];
            }
#pragma unroll
            for (int nt = 0; nt < 16; nt++) {
                mma_f16(O[nt], ph[ks], vb[nt]);
                mma_f16(O[nt], pl[ks], vb[nt]);
            }
#pragma unroll
            for (int jp = 0; jp < 8; jp++) {
                int r = ks * 16 + (lane & 15);
                int u = jp * 2 + (lane >> 4);
                uint32_t t[4];
                ldsm4t(t, smem_u32(Vbl + r * 136 + u * 8));
                vb[2 * jp][0] = t[0]; vb[2 * jp][1] = t[1];
                vb[2 * jp + 1][0] = t[2]; vb[2 * jp + 1][1] = t[3];
            }
#pragma unroll
            for (int nt = 0; nt < 16; nt++) {
                mma_f16(O[nt], ph[ks], vb[nt]);
            }
        }
    }

    float sink = sinks[h];
    l0 += __expf(sink - m0);
    l1 += __expf(sink - m1);
    float i0 = 1.f / l0, i1 = 1.f / l1;
    int row0 = qt * 128 + w * 16 + gid;
#pragma unroll
    for (int nt = 0; nt < 16; nt++) {
        int col = h * 128 + nt * 8 + tig * 2;
        float f0 = O[nt][0] * i0, f1 = O[nt][1] * i0;
        float f2 = O[nt][2] * i1, f3 = O[nt][3] * i1;
        __half h0 = __float2half_rn(f0), h1 = __float2half_rn(f1);
        __half h2 = __float2half_rn(f2), h3 = __float2half_rn(f3);
        __half2 u01; u01.x = h0; u01.y = h1;
        __half2 u23; u23.x = h2; u23.y = h3;
        *(__half2*)&ath[(size_t)row0 * 4096 + col] = u01;
        *(__half2*)&ath[(size_t)(row0 + 8) * 4096 + col] = u23;
        *(uint32_t*)&atl[(size_t)row0 * 4096 + col] =
            pack_h2(f0 - __half2float(h0), f1 - __half2float(h1));
        *(uint32_t*)&atl[(size_t)(row0 + 8) * 4096 + col] =
            pack_h2(f2 - __half2float(h2), f3 - __half2float(h3));
    }
}

// ---------------------------------------------------------------------------
extern "C" void kernel_launch(void* const* d_in, const int* in_sizes, int n_in,
                              void* d_out, int out_size)
{
    const float* X_in  = (const float*)d_in[0];
    const float* cosb  = (const float*)d_in[1];
    const float* sinb  = (const float*)d_in[2];
    const float* Wq_in = (const float*)d_in[4];
    const float* Wk_in = (const float*)d_in[5];
    const float* Wv_in = (const float*)d_in[6];
    const float* Wo_in = (const float*)d_in[7];
    const float* sinks = (const float*)d_in[8];
    float* out = (float*)d_out;

    __half *Xh, *Wqkv, *Woh, *qh, *ql, *kh, *vh, *vl, *ath, *atl;
    float *qkvf;
    cudaGetSymbolAddress((void**)&Xh,   g_Xh);
    cudaGetSymbolAddress((void**)&Wqkv, g_Wqkv);
    cudaGetSymbolAddress((void**)&Woh,  g_Woh);
    cudaGetSymbolAddress((void**)&qkvf, g_qkvf);
    cudaGetSymbolAddress((void**)&qh,   g_qh);
    cudaGetSymbolAddress((void**)&ql,   g_ql);
    cudaGetSymbolAddress((void**)&kh,   g_kh);
    cudaGetSymbolAddress((void**)&vh,   g_vh);
    cudaGetSymbolAddress((void**)&vl,   g_vl);
    cudaGetSymbolAddress((void**)&ath,  g_ath);
    cudaGetSymbolAddress((void**)&atl,  g_atl);

    cudaFuncSetAttribute((const void*)hgemm1, cudaFuncAttributeMaxDynamicSharedMemorySize, PSMEM1);
    cudaFuncSetAttribute((const void*)hgemm2, cudaFuncAttributeMaxDynamicSharedMemorySize, PSMEM2);
    cudaFuncSetAttribute((const void*)flash_kernel, cudaFuncAttributeMaxDynamicSharedMemorySize, FSMEM);

    // 0. prep
    split1_kernel<<<2048, 256>>>(X_in, Xh, SEQ * HID);
    wqkv_pack<<<8192, 256>>>(Wq_in, Wk_in, Wv_in, Wqkv);
    split1_kernel<<<4096, 256>>>(Wo_in, Woh, 4096 * HID);

    // 1. fused QKV projection (single-A): qkvf = Xh @ Wqkv
    hgemm1<<<dim3(6144 / 128, SEQ / 128), 128, PSMEM1>>>(Xh, Wqkv, qkvf,
                                                         SEQ, 6144, HID, HID, 6144, 6144);

    // 2. RoPE + splits
    rope_split_kernel<<<SEQ * 40 / 8, 256>>>(qkvf, cosb, sinb, qh, ql, kh);
    vsplit_kernel<<<1024, 256>>>(qkvf, vh, vl);

    // 3. flash attention
    flash_kernel<<<dim3(16, 32), 256, FSMEM>>>(qh, ql, kh, vh, vl, sinks, ath, atl);

    // 4. output projection (dual-A): out = (ath+atl) @ Woh
    hgemm2<<<dim3(4096 / 128, SEQ / 128), 128, PSMEM2>>>(ath, atl, Woh, out,
                                                         SEQ, HID, 4096, 4096, HID, HID);
}

// round 12
// speedup vs baseline: 1.2666x; 1.0603x over previous
#include <cuda_runtime.h>
#include <cuda_fp16.h>
#include <cstdint>

#define SEQ 2048
#define HID 4096
#define NH  32
#define NKV 8
#define HD  128
#define SCALE 0.08838834764831845f

// ---------------- scratch (device globals; no allocations) ----------------
__device__ __half g_Xh  [(size_t)SEQ * HID];
__device__ __half g_Wqkv[(size_t)HID * 6144];   // [Wq | Wk | Wv] fp16 [K,N]
__device__ __half g_Woh [(size_t)4096 * HID];   // Wo fp16 [K,N]
__device__ float  g_qkvf[(size_t)SEQ * 6144];
__device__ __half g_qh  [(size_t)SEQ * 4096];
__device__ __half g_ql  [(size_t)SEQ * 4096];
__device__ __half g_kh  [(size_t)SEQ * 1024];
__device__ __half g_vh  [(size_t)SEQ * 1024];
__device__ __half g_vl  [(size_t)SEQ * 1024];
__device__ __half g_ath [(size_t)SEQ * 4096];
__device__ __half g_atl [(size_t)SEQ * 4096];

// ---------------- helpers ----------------
__device__ __forceinline__ uint32_t smem_u32(const void* p) {
    return (uint32_t)__cvta_generic_to_shared(p);
}
__device__ __forceinline__ void cp16(uint32_t s, const void* g) {
    asm volatile("cp.async.cg.shared.global [%0], [%1], 16;\n" :: "r"(s), "l"(g));
}
#define CP_COMMIT() asm volatile("cp.async.commit_group;")
#define CP_WAIT(n)  asm volatile("cp.async.wait_group %0;" :: "n"(n))

__device__ __forceinline__ void ldsm4(uint32_t* r, uint32_t a) {
    asm volatile("ldmatrix.sync.aligned.m8n8.x4.shared.b16 {%0,%1,%2,%3}, [%4];"
                 : "=r"(r[0]), "=r"(r[1]), "=r"(r[2]), "=r"(r[3]) : "r"(a));
}
__device__ __forceinline__ void ldsm4t(uint32_t* r, uint32_t a) {
    asm volatile("ldmatrix.sync.aligned.m8n8.x4.trans.shared.b16 {%0,%1,%2,%3}, [%4];"
                 : "=r"(r[0]), "=r"(r[1]), "=r"(r[2]), "=r"(r[3]) : "r"(a));
}
__device__ __forceinline__ void mma_f16(float* c, const uint32_t* a, const uint32_t* b) {
    asm volatile("mma.sync.aligned.m16n8k16.row.col.f32.f16.f16.f32 "
                 "{%0,%1,%2,%3},{%4,%5,%6,%7},{%8,%9},{%0,%1,%2,%3};"
                 : "+f"(c[0]), "+f"(c[1]), "+f"(c[2]), "+f"(c[3])
                 : "r"(a[0]), "r"(a[1]), "r"(a[2]), "r"(a[3]), "r"(b[0]), "r"(b[1]));
}
__device__ __forceinline__ uint32_t pack_h2(float a, float b) {
    __half2 t = __floats2half2_rn(a, b);
    return *reinterpret_cast<uint32_t*>(&t);
}

// ---------------- prep kernels ----------------
__global__ void split1_kernel(const float* __restrict__ s, __half* __restrict__ d, int n) {
    for (int i = blockIdx.x * blockDim.x + threadIdx.x; i < n; i += gridDim.x * blockDim.x)
        d[i] = __float2half_rn(s[i]);
}
__global__ void wqkv_pack(const float* __restrict__ Wq, const float* __restrict__ Wk,
                          const float* __restrict__ Wv, __half* __restrict__ d) {
    const int n = HID * 6144;
    for (int i = blockIdx.x * blockDim.x + threadIdx.x; i < n; i += gridDim.x * blockDim.x) {
        int r = i / 6144, c = i - r * 6144;
        float x;
        if (c < 4096)      x = Wq[(size_t)r * 4096 + c];
        else if (c < 5120) x = Wk[(size_t)r * 1024 + (c - 4096)];
        else               x = Wv[(size_t)r * 1024 + (c - 5120)];
        d[i] = __float2half_rn(x);
    }
}
// RoPE (q scaled, hi/lo; k hi) + V hi/lo split, one kernel.
// warp-job hh: 0..31 q-head, 32..39 k-head, 40..47 v-head.
__global__ void rope_v_kernel(const float* __restrict__ qkvf,
                              const float* __restrict__ cosb, const float* __restrict__ sinb,
                              __half* __restrict__ qh, __half* __restrict__ ql,
                              __half* __restrict__ kh,
                              __half* __restrict__ vh, __half* __restrict__ vl)
{
    int gw = blockIdx.x * 8 + (threadIdx.x >> 5);
    int lane = threadIdx.x & 31;
    int s = gw / 48, hh = gw % 48;
    if (s >= SEQ) return;

    if (hh >= 40) {   // V split
        const float* src = qkvf + (size_t)s * 6144 + 5120 + (hh - 40) * 128;
        size_t base = (size_t)s * 1024 + (hh - 40) * 128;
#pragma unroll
        for (int i = 0; i < 4; i++) {
            float x = src[i * 32 + lane];
            __half h = __float2half_rn(x);
            vh[base + i * 32 + lane] = h;
            vl[base + i * 32 + lane] = __float2half_rn(x - __half2float(h));
        }
        return;
    }

    float c0 = cosb[(size_t)s * 64 + lane];
    float s0 = sinb[(size_t)s * 64 + lane];
    float c1 = cosb[(size_t)s * 64 + 32 + lane];
    float s1 = sinb[(size_t)s * 64 + 32 + lane];

    if (hh < NH) {
        const float* src = qkvf + (size_t)s * 6144 + hh * 128;
        float x0 = src[lane], x1 = src[32 + lane], x2 = src[64 + lane], x3 = src[96 + lane];
        float v[4];
        v[0] = (x0 * c0 - x1 * s0) * SCALE;
        v[1] = (x1 * c1 + x0 * s1) * SCALE;
        v[2] = x2 * SCALE;
        v[3] = x3 * SCALE;
        size_t base = (size_t)s * 4096 + hh * 128;
        const int off[4] = {0, 32, 64, 96};
#pragma unroll
        for (int i = 0; i < 4; i++) {
            __half h = __float2half_rn(v[i]);
            qh[base + off[i] + lane] = h;
            ql[base + off[i] + lane] = __float2half_rn(v[i] - __half2float(h));
        }
    } else {
        const float* src = qkvf + (size_t)s * 6144 + 4096 + (hh - NH) * 128;
        float x0 = src[lane], x1 = src[32 + lane], x2 = src[64 + lane], x3 = src[96 + lane];
        size_t base = (size_t)s * 1024 + (hh - NH) * 128;
        kh[base + lane]      = __float2half_rn(x0 * c0 - x1 * s0);
        kh[base + 32 + lane] = __float2half_rn(x1 * c1 + x0 * s1);
        kh[base + 64 + lane] = __float2half_rn(x2);
        kh[base + 96 + lane] = __float2half_rn(x3);
    }
}

// ---------------------------------------------------------------------------
// hgemm1: C = Ah * B (single-A). CTA 128x128 k32, 4 warps, 4-stage cp.async.
// stage halves: Ah 128x40 (5120) | B 32x136 (4352) = 9472
// ---------------------------------------------------------------------------
#define PSTG1 9472
#define PSMEM1 (4 * PSTG1 * 2)

__global__ __launch_bounds__(128, 3)
void hgemm1(const __half* __restrict__ Ah, const __half* __restrict__ B,
            float* __restrict__ C, int M, int N, int K, int lda, int ldb, int ldc)
{
    extern __shared__ __half sm[];
    const int bm = blockIdx.y, bn = blockIdx.x;
    const int tid = threadIdx.x, lane = tid & 31, warp = tid >> 5;
    const int wm = warp & 1, wn = warp >> 1;

    const __half* Agh = Ah + (size_t)bm * 128 * lda;
    const __half* Bg  = B + bn * 128;

    auto load_stage = [&](int st, int k0) {
        __half* sa = sm + st * PSTG1;
        __half* sb = sa + 5120;
#pragma unroll
        for (int i = 0; i < 4; i++) {
            int id = tid + i * 128;
            int r = id >> 2, u = id & 3;
            cp16(smem_u32(sa + r * 40 + u * 8), Agh + (size_t)r * lda + k0 + u * 8);
        }
#pragma unroll
        for (int i = 0; i < 4; i++) {
            int id = tid + i * 128;
            int r = id >> 4, u = id & 15;
            cp16(smem_u32(sb + r * 136 + u * 8), Bg + (size_t)(k0 + r) * ldb + u * 8);
        }
    };

    float acc[4][8][4];
#pragma unroll
    for (int a = 0; a < 4; a++)
#pragma unroll
        for (int b = 0; b < 8; b++)
#pragma unroll
            for (int c = 0; c < 4; c++) acc[a][b][c] = 0.f;

    const int nk = K >> 5;
    load_stage(0, 0);  CP_COMMIT();
    load_stage(1, 32); CP_COMMIT();
    load_stage(2, 64); CP_COMMIT();
    CP_WAIT(2);
    __syncthreads();

    for (int it = 0; it < nk; it++) {
        int nx = it + 3;
        if (nx < nk) load_stage(nx & 3, nx * 32);
        CP_COMMIT();

        const __half* sa = sm + (it & 3) * PSTG1;
        const __half* sb = sa + 5120;
#pragma unroll
        for (int kk = 0; kk < 2; kk++) {
            uint32_t ah[4][4], bb[8][2];
#pragma unroll
            for (int im = 0; im < 4; im++) {
                int r = wm * 64 + im * 16 + (lane & 15);
                int u = kk * 2 + (lane >> 4);
                ldsm4(ah[im], smem_u32(sa + r * 40 + u * 8));
            }
#pragma unroll
            for (int jp = 0; jp < 4; jp++) {
                int r = kk * 16 + (lane & 15);
                int u = wn * 8 + jp * 2 + (lane >> 4);
                uint32_t t[4];
                ldsm4t(t, smem_u32(sb + r * 136 + u * 8));
                bb[2 * jp][0] = t[0]; bb[2 * jp][1] = t[1];
                bb[2 * jp + 1][0] = t[2]; bb[2 * jp + 1][1] = t[3];
            }
#pragma unroll
            for (int im = 0; im < 4; im++)
#pragma unroll
                for (int jn = 0; jn < 8; jn++)
                    mma_f16(acc[im][jn], ah[im], bb[jn]);
        }
        CP_WAIT(2);
        __syncthreads();
    }

    const int gid = lane >> 2, tig = lane & 3;
#pragma unroll
    for (int im = 0; im < 4; im++) {
        int row = bm * 128 + wm * 64 + im * 16 + gid;
#pragma unroll
        for (int jn = 0; jn < 8; jn++) {
            int col = bn * 128 + wn * 64 + jn * 8 + tig * 2;
            *(float2*)&C[(size_t)row * ldc + col] = make_float2(acc[im][jn][0], acc[im][jn][1]);
            *(float2*)&C[(size_t)(row + 8) * ldc + col] = make_float2(acc[im][jn][2], acc[im][jn][3]);
        }
    }
}

// ---------------------------------------------------------------------------
// hgemm2: C = (Ah + Al) * B (dual-A; proven R6 kernel, 3-stage)
// ---------------------------------------------------------------------------
#define PSTG2 14592
#define PSMEM2 (3 * PSTG2 * 2)

__global__ __launch_bounds__(128, 2)
void hgemm2(const __half* __restrict__ Ah, const __half* __restrict__ Al,
            const __half* __restrict__ B, float* __restrict__ C,
            int M, int N, int K, int lda, int ldb, int ldc)
{
    extern __shared__ __half sm[];
    const int bm = blockIdx.y, bn = blockIdx.x;
    const int tid = threadIdx.x, lane = tid & 31, warp = tid >> 5;
    const int wm = warp & 1, wn = warp >> 1;

    const __half* Agh = Ah + (size_t)bm * 128 * lda;
    const __half* Agl = Al + (size_t)bm * 128 * lda;
    const __half* Bg  = B + bn * 128;

    auto load_stage = [&](int st, int k0) {
        __half* sa = sm + st * PSTG2;
        __half* sl = sa + 5120;
        __half* sb = sl + 5120;
#pragma unroll
        for (int i = 0; i < 4; i++) {
            int id = tid + i * 128;
            int r = id >> 2, u = id & 3;
            cp16(smem_u32(sa + r * 40 + u * 8), Agh + (size_t)r * lda + k0 + u * 8);
            cp16(smem_u32(sl + r * 40 + u * 8), Agl + (size_t)r * lda + k0 + u * 8);
        }
#pragma unroll
        for (int i = 0; i < 4; i++) {
            int id = tid + i * 128;
            int r = id >> 4, u = id & 15;
            cp16(smem_u32(sb + r * 136 + u * 8), Bg + (size_t)(k0 + r) * ldb + u * 8);
        }
    };

    float acc[4][8][4];
#pragma unroll
    for (int a = 0; a < 4; a++)
#pragma unroll
        for (int b = 0; b < 8; b++)
#pragma unroll
            for (int c = 0; c < 4; c++) acc[a][b][c] = 0.f;

    const int nk = K >> 5;
    load_stage(0, 0);  CP_COMMIT();
    load_stage(1, 32); CP_COMMIT();
    CP_WAIT(1);
    __syncthreads();

    for (int it = 0; it < nk; it++) {
        int cur = it % 3;
        int nx = it + 2;
        if (nx < nk) load_stage(nx % 3, nx * 32);
        CP_COMMIT();

        const __half* sa = sm + cur * PSTG2;
        const __half* sl = sa + 5120;
        const __half* sb = sl + 5120;
#pragma unroll
        for (int kk = 0; kk < 2; kk++) {
            uint32_t ah[4][4], al[4][4], bb[8][2];
#pragma unroll
            for (int im = 0; im < 4; im++) {
                int r = wm * 64 + im * 16 + (lane & 15);
                int u = kk * 2 + (lane >> 4);
                ldsm4(ah[im], smem_u32(sa + r * 40 + u * 8));
                ldsm4(al[im], smem_u32(sl + r * 40 + u * 8));
            }
#pragma unroll
            for (int jp = 0; jp < 4; jp++) {
                int r = kk * 16 + (lane & 15);
                int u = wn * 8 + jp * 2 + (lane >> 4);
                uint32_t t[4];
                ldsm4t(t, smem_u32(sb + r * 136 + u * 8));
                bb[2 * jp][0] = t[0]; bb[2 * jp][1] = t[1];
                bb[2 * jp + 1][0] = t[2]; bb[2 * jp + 1][1] = t[3];
            }
#pragma unroll
            for (int im = 0; im < 4; im++)
#pragma unroll
                for (int jn = 0; jn < 8; jn++) {
                    mma_f16(acc[im][jn], ah[im], bb[jn]);
                    mma_f16(acc[im][jn], al[im], bb[jn]);
                }
        }
        CP_WAIT(1);
        __syncthreads();
    }

    const int gid = lane >> 2, tig = lane & 3;
#pragma unroll
    for (int im = 0; im < 4; im++) {
        int row = bm * 128 + wm * 64 + im * 16 + gid;
#pragma unroll
        for (int jn = 0; jn < 8; jn++) {
            int col = bn * 128 + wn * 64 + jn * 8 + tig * 2;
            *(float2*)&C[(size_t)row * ldc + col] = make_float2(acc[im][jn][0], acc[im][jn][1]);
            *(float2*)&C[(size_t)(row + 8) * ldc + col] = make_float2(acc[im][jn][2], acc[im][jn][3]);
        }
    }
}

// ---------------------------------------------------------------------------
// Flash attention, 128-wide KV tiles. CTA: 128 q-rows (8 warps x 16), nkt=qt+1.
// K double-buffered, Vh/Vl single-buffered (loaded for tile kt during tile
// kt-1's PV epilogue; overlaps QK+softmax of tile kt). Q/P x2 splits, V x2
// chains (PhVh + PlVh + PhVl) -- numerics identical to R6/R11.
// smem halves: Qh 17408 | Ql 17408 | K 2x17408 | Vh 17408 | Vl 17408
// ---------------------------------------------------------------------------
#define FT 17408   // 128*136
#define FSMEM (6 * FT * 2)

__global__ __launch_bounds__(256, 1)
void flash_kernel(const __half* __restrict__ qh, const __half* __restrict__ ql,
                  const __half* __restrict__ kh,
                  const __half* __restrict__ vh, const __half* __restrict__ vl,
                  const float* __restrict__ sinks,
                  __half* __restrict__ ath, __half* __restrict__ atl)
{
    extern __shared__ __half sm[];
    __half* Qh = sm;
    __half* Ql = Qh + FT;
    __half* Ks = Ql + FT;        // 2 buffers
    __half* Vs = Ks + 2 * FT;    // single
    __half* Vx = Vs + FT;        // single

    const int qt = gridDim.x - 1 - blockIdx.x;
    const int h = blockIdx.y, kvh = h >> 2;
    const int tid = threadIdx.x, lane = tid & 31, w = tid >> 5;
    const int gid = lane >> 2, tig = lane & 3;

    // Q tiles (hi, lo) + K0 in first group
    {
        const __half* src = qh + (size_t)(qt * 128) * 4096 + h * 128;
        const __half* srl = ql + (size_t)(qt * 128) * 4096 + h * 128;
#pragma unroll
        for (int i = 0; i < 8; i++) {
            int id = tid + i * 256;
            int r = id >> 4, u = id & 15;
            cp16(smem_u32(Qh + r * 136 + u * 8), src + (size_t)r * 4096 + u * 8);
            cp16(smem_u32(Ql + r * 136 + u * 8), srl + (size_t)r * 4096 + u * 8);
        }
    }
    auto loadK = [&](int kt) {
        __half* dst = Ks + (kt & 1) * FT;
        const __half* src = kh + (size_t)(kt * 128) * 1024 + kvh * 128;
#pragma unroll
        for (int i = 0; i < 8; i++) {
            int id = tid + i * 256;
            int r = id >> 4, u = id & 15;
            cp16(smem_u32(dst + r * 136 + u * 8), src + (size_t)r * 1024 + u * 8);
        }
    };
    auto loadV = [&](int kt) {
        const __half* sv = vh + (size_t)(kt * 128) * 1024 + kvh * 128;
        const __half* sx = vl + (size_t)(kt * 128) * 1024 + kvh * 128;
#pragma unroll
        for (int i = 0; i < 8; i++) {
            int id = tid + i * 256;
            int r = id >> 4, u = id & 15;
            cp16(smem_u32(Vs + r * 136 + u * 8), sv + (size_t)r * 1024 + u * 8);
            cp16(smem_u32(Vx + r * 136 + u * 8), sx + (size_t)r * 1024 + u * 8);
        }
    };

    loadK(0);
    CP_COMMIT();     // group: Q + K0
    loadV(0);
    CP_COMMIT();     // group: V0

    float m0 = -1e30f, m1 = -1e30f, l0 = 0.f, l1 = 0.f;
    float O[16][4];
#pragma unroll
    for (int i = 0; i < 16; i++)
#pragma unroll
        for (int j = 0; j < 4; j++) O[i][j] = 0.f;

    const int nkt = qt + 1;
    const int rowg0 = qt * 128 + w * 16 + gid;

    for (int kt = 0; kt < nkt; kt++) {
        // pending: [K(kt)(+Q), V(kt)] -> retire K(kt)
        CP_WAIT(1);
        __syncthreads();

        const __half* Kb = Ks + (kt & 1) * FT;

        // ---- S = Q K^T over 128 keys (Q x2) ----
        float S[16][4];
#pragma unroll
        for (int i = 0; i < 16; i++)
#pragma unroll
            for (int j = 0; j < 4; j++) S[i][j] = 0.f;
#pragma unroll
        for (int kk = 0; kk < 8; kk++) {
            uint32_t qa[4], qb[4], kb[16][2];
            {
                int r = w * 16 + (lane & 15);
                int u = kk * 2 + (lane >> 4);
                ldsm4(qa, smem_u32(Qh + r * 136 + u * 8));
                ldsm4(qb, smem_u32(Ql + r * 136 + u * 8));
            }
#pragma unroll
            for (int jp = 0; jp < 8; jp++) {
                int r = jp * 16 + (lane & 15);
                int u = kk * 2 + (lane >> 4);
                uint32_t t[4];
                ldsm4(t, smem_u32(Kb + r * 136 + u * 8));
                kb[2 * jp][0] = t[0]; kb[2 * jp][1] = t[2];
                kb[2 * jp + 1][0] = t[1]; kb[2 * jp + 1][1] = t[3];
            }
#pragma unroll
            for (int jn = 0; jn < 16; jn++) {
                mma_f16(S[jn], qa, kb[jn]);
                mma_f16(S[jn], qb, kb[jn]);
            }
        }

        // prefetch K(kt+1) into the other buffer (read in next iter)
        if (kt + 1 < nkt) loadK(kt + 1);
        CP_COMMIT();

        // ---- causal mask (last tile only; tile == diagonal block) ----
        if (kt == nkt - 1) {
#pragma unroll
            for (int jn = 0; jn < 16; jn++) {
                int colb = kt * 128 + jn * 8 + tig * 2;
                if (colb > rowg0)         S[jn][0] = -1e30f;
                if (colb + 1 > rowg0)     S[jn][1] = -1e30f;
                if (colb > rowg0 + 8)     S[jn][2] = -1e30f;
                if (colb + 1 > rowg0 + 8) S[jn][3] = -1e30f;
            }
        }

        // ---- online softmax over the 128-key tile ----
        float mr0 = -1e30f, mr1 = -1e30f;
#pragma unroll
        for (int jn = 0; jn < 16; jn++) {
            mr0 = fmaxf(mr0, fmaxf(S[jn][0], S[jn][1]));
            mr1 = fmaxf(mr1, fmaxf(S[jn][2], S[jn][3]));
        }
        mr0 = fmaxf(mr0, __shfl_xor_sync(0xffffffff, mr0, 1));
        mr0 = fmaxf(mr0, __shfl_xor_sync(0xffffffff, mr0, 2));
        mr1 = fmaxf(mr1, __shfl_xor_sync(0xffffffff, mr1, 1));
        mr1 = fmaxf(mr1, __shfl_xor_sync(0xffffffff, mr1, 2));
        float mn0 = fmaxf(m0, mr0), mn1 = fmaxf(m1, mr1);
        float a0 = __expf(m0 - mn0), a1 = __expf(m1 - mn1);

        float sum0 = 0.f, sum1 = 0.f;
#pragma unroll
        for (int jn = 0; jn < 16; jn++) {
            S[jn][0] = __expf(S[jn][0] - mn0);
            S[jn][1] = __expf(S[jn][1] - mn0);
            S[jn][2] = __expf(S[jn][2] - mn1);
            S[jn][3] = __expf(S[jn][3] - mn1);
            sum0 += S[jn][0] + S[jn][1];
            sum1 += S[jn][2] + S[jn][3];
        }
        sum0 += __shfl_xor_sync(0xffffffff, sum0, 1);
        sum0 += __shfl_xor_sync(0xffffffff, sum0, 2);
        sum1 += __shfl_xor_sync(0xffffffff, sum1, 1);
        sum1 += __shfl_xor_sync(0xffffffff, sum1, 2);
        l0 = l0 * a0 + sum0;
        l1 = l1 * a1 + sum1;
        m0 = mn0; m1 = mn1;
#pragma unroll
        for (int nt = 0; nt < 16; nt++) {
            O[nt][0] *= a0; O[nt][1] *= a0;
            O[nt][2] *= a1; O[nt][3] *= a1;
        }

        // pending: [V(kt), K(kt+1)] -> retire V(kt)
        CP_WAIT(1);
        __syncthreads();

        // ---- O += P V (P x2, V x2: PhVh + PlVh + PhVl); pack P per ks ----
#pragma unroll
        for (int ks = 0; ks < 8; ks++) {
            uint32_t ph[4], pl[4];
#pragma unroll
            for (int t = 0; t < 2; t++) {
                float p0 = S[2 * ks + t][0], p1 = S[2 * ks + t][1];
                float p2 = S[2 * ks + t][2], p3 = S[2 * ks + t][3];
                __half h0 = __float2half_rn(p0), h1 = __float2half_rn(p1);
                __half h2 = __float2half_rn(p2), h3 = __float2half_rn(p3);
                __half2 u01; u01.x = h0; u01.y = h1;
                __half2 u23; u23.x = h2; u23.y = h3;
                ph[2 * t + 0] = *(uint32_t*)&u01;
                ph[2 * t + 1] = *(uint32_t*)&u23;
                pl[2 * t + 0] = pack_h2(p0 - __half2float(h0), p1 - __half2float(h1));
                pl[2 * t + 1] = pack_h2(p2 - __half2float(h2), p3 - __half2float(h3));
            }
            uint32_t vb[16][2];
#pragma unroll
            for (int jp = 0; jp < 8; jp++) {
                int r = ks * 16 + (lane & 15);
                int u = jp * 2 + (lane >> 4);
                uint32_t t[4];
                ldsm4t(t, smem_u32(Vs + r * 136 + u * 8));
                vb[2 * jp][0] = t[0]; vb[2 * jp][1] = t[1];
                vb[2 * jp + 1][0] = t[2]; vb[2 * jp + 1][1] = t[3];
            }
#pragma unroll
            for (int nt = 0; nt < 16; nt++) {
                mma_f16(O[nt], ph, vb[nt]);
                mma_f16(O[nt], pl, vb[nt]);
            }
#pragma unroll
            for (int jp = 0; jp < 8; jp++) {
                int r = ks * 16 + (lane & 15);
                int u = jp * 2 + (lane >> 4);
                uint32_t t[4];
                ldsm4t(t, smem_u32(Vx + r * 136 + u * 8));
                vb[2 * jp][0] = t[0]; vb[2 * jp][1] = t[1];
                vb[2 * jp + 1][0] = t[2]; vb[2 * jp + 1][1] = t[3];
            }
#pragma unroll
            for (int nt = 0; nt < 16; nt++) {
                mma_f16(O[nt], ph, vb[nt]);
            }
        }

        // all warps done reading V buffers -> safe to overwrite
        __syncthreads();
        if (kt + 1 < nkt) loadV(kt + 1);
        CP_COMMIT();
    }

    // ---- sink + normalize + store hi/lo ----
    float sink = sinks[h];
    l0 += __expf(sink - m0);
    l1 += __expf(sink - m1);
    float i0 = 1.f / l0, i1 = 1.f / l1;
    int row0 = qt * 128 + w * 16 + gid;
#pragma unroll
    for (int nt = 0; nt < 16; nt++) {
        int col = h * 128 + nt * 8 + tig * 2;
        float f0 = O[nt][0] * i0, f1 = O[nt][1] * i0;
        float f2 = O[nt][2] * i1, f3 = O[nt][3] * i1;
        __half h0 = __float2half_rn(f0), h1 = __float2half_rn(f1);
        __half h2 = __float2half_rn(f2), h3 = __float2half_rn(f3);
        __half2 u01; u01.x = h0; u01.y = h1;
        __half2 u23; u23.x = h2; u23.y = h3;
        *(__half2*)&ath[(size_t)row0 * 4096 + col] = u01;
        *(__half2*)&ath[(size_t)(row0 + 8) * 4096 + col] = u23;
        *(uint32_t*)&atl[(size_t)row0 * 4096 + col] =
            pack_h2(f0 - __half2float(h0), f1 - __half2float(h1));
        *(uint32_t*)&atl[(size_t)(row0 + 8) * 4096 + col] =
            pack_h2(f2 - __half2float(h2), f3 - __half2float(h3));
    }
}

// ---------------------------------------------------------------------------
extern "C" void kernel_launch(void* const* d_in, const int* in_sizes, int n_in,
                              void* d_out, int out_size)
{
    const float* X_in  = (const float*)d_in[0];
    const float* cosb  = (const float*)d_in[1];
    const float* sinb  = (const float*)d_in[2];
    const float* Wq_in = (const float*)d_in[4];
    const float* Wk_in = (const float*)d_in[5];
    const float* Wv_in = (const float*)d_in[6];
    const float* Wo_in = (const float*)d_in[7];
    const float* sinks = (const float*)d_in[8];
    float* out = (float*)d_out;

    __half *Xh, *Wqkv, *Woh, *qh, *ql, *kh, *vh, *vl, *ath, *atl;
    float *qkvf;
    cudaGetSymbolAddress((void**)&Xh,   g_Xh);
    cudaGetSymbolAddress((void**)&Wqkv, g_Wqkv);
    cudaGetSymbolAddress((void**)&Woh,  g_Woh);
    cudaGetSymbolAddress((void**)&qkvf, g_qkvf);
    cudaGetSymbolAddress((void**)&qh,   g_qh);
    cudaGetSymbolAddress((void**)&ql,   g_ql);
    cudaGetSymbolAddress((void**)&kh,   g_kh);
    cudaGetSymbolAddress((void**)&vh,   g_vh);
    cudaGetSymbolAddress((void**)&vl,   g_vl);
    cudaGetSymbolAddress((void**)&ath,  g_ath);
    cudaGetSymbolAddress((void**)&atl,  g_atl);

    cudaFuncSetAttribute((const void*)hgemm1, cudaFuncAttributeMaxDynamicSharedMemorySize, PSMEM1);
    cudaFuncSetAttribute((const void*)hgemm2, cudaFuncAttributeMaxDynamicSharedMemorySize, PSMEM2);
    cudaFuncSetAttribute((const void*)flash_kernel, cudaFuncAttributeMaxDynamicSharedMemorySize, FSMEM);

    // 0. prep
    split1_kernel<<<2048, 256>>>(X_in, Xh, SEQ * HID);
    wqkv_pack<<<8192, 256>>>(Wq_in, Wk_in, Wv_in, Wqkv);
    split1_kernel<<<4096, 256>>>(Wo_in, Woh, 4096 * HID);

    // 1. fused QKV projection (single-A): qkvf = Xh @ Wqkv
    hgemm1<<<dim3(6144 / 128, SEQ / 128), 128, PSMEM1>>>(Xh, Wqkv, qkvf,
                                                         SEQ, 6144, HID, HID, 6144, 6144);

    // 2. RoPE + q/k/v splits (one kernel)
    rope_v_kernel<<<SEQ * 48 / 8, 256>>>(qkvf, cosb, sinb, qh, ql, kh, vh, vl);

    // 3. flash attention (128-wide KV tiles)
    flash_kernel<<<dim3(16, 32), 256, FSMEM>>>(qh, ql, kh, vh, vl, sinks, ath, atl);

    // 4. output projection (dual-A): out = (ath+atl) @ Woh
    hgemm2<<<dim3(4096 / 128, SEQ / 128), 128, PSMEM2>>>(ath, atl, Woh, out,
                                                         SEQ, HID, 4096, 4096, HID, HID);
}

// round 14
// speedup vs baseline: 1.4563x; 1.1498x over previous
#include <cuda_runtime.h>
#include <cuda_fp16.h>
#include <cstdint>

#define SEQ 2048
#define HID 4096
#define NH  32
#define NKV 8
#define HD  128
#define SCALE 0.08838834764831845f

// ---------------- scratch (device globals; no allocations) ----------------
__device__ __half g_Xh  [(size_t)SEQ * HID];
__device__ __half g_Wqkv[(size_t)HID * 6144];   // [Wq | Wk | Wv] fp16 [K,N]
__device__ __half g_Woh [(size_t)4096 * HID];   // Wo fp16 [K,N]
__device__ float  g_qkvf[(size_t)SEQ * 6144];
__device__ __half g_qh  [(size_t)SEQ * 4096];
__device__ __half g_ql  [(size_t)SEQ * 4096];
__device__ __half g_kh  [(size_t)SEQ * 1024];
__device__ __half g_vh  [(size_t)SEQ * 1024];
__device__ __half g_vl  [(size_t)SEQ * 1024];
__device__ __half g_ath [(size_t)SEQ * 4096];

// ---------------- helpers ----------------
__device__ __forceinline__ uint32_t smem_u32(const void* p) {
    return (uint32_t)__cvta_generic_to_shared(p);
}
__device__ __forceinline__ void cp16(uint32_t s, const void* g) {
    asm volatile("cp.async.cg.shared.global [%0], [%1], 16;\n" :: "r"(s), "l"(g));
}
#define CP_COMMIT() asm volatile("cp.async.commit_group;")
#define CP_WAIT(n)  asm volatile("cp.async.wait_group %0;" :: "n"(n))

__device__ __forceinline__ void ldsm4(uint32_t* r, uint32_t a) {
    asm volatile("ldmatrix.sync.aligned.m8n8.x4.shared.b16 {%0,%1,%2,%3}, [%4];"
                 : "=r"(r[0]), "=r"(r[1]), "=r"(r[2]), "=r"(r[3]) : "r"(a));
}
__device__ __forceinline__ void ldsm4t(uint32_t* r, uint32_t a) {
    asm volatile("ldmatrix.sync.aligned.m8n8.x4.trans.shared.b16 {%0,%1,%2,%3}, [%4];"
                 : "=r"(r[0]), "=r"(r[1]), "=r"(r[2]), "=r"(r[3]) : "r"(a));
}
__device__ __forceinline__ void mma_f16(float* c, const uint32_t* a, const uint32_t* b) {
    asm volatile("mma.sync.aligned.m16n8k16.row.col.f32.f16.f16.f32 "
                 "{%0,%1,%2,%3},{%4,%5,%6,%7},{%8,%9},{%0,%1,%2,%3};"
                 : "+f"(c[0]), "+f"(c[1]), "+f"(c[2]), "+f"(c[3])
                 : "r"(a[0]), "r"(a[1]), "r"(a[2]), "r"(a[3]), "r"(b[0]), "r"(b[1]));
}
__device__ __forceinline__ uint32_t pack_h2(float a, float b) {
    __half2 t = __floats2half2_rn(a, b);
    return *reinterpret_cast<uint32_t*>(&t);
}

// ---------------- prep kernels ----------------
__global__ void split1_kernel(const float* __restrict__ s, __half* __restrict__ d, int n) {
    for (int i = blockIdx.x * blockDim.x + threadIdx.x; i < n; i += gridDim.x * blockDim.x)
        d[i] = __float2half_rn(s[i]);
}
__global__ void wqkv_pack(const float* __restrict__ Wq, const float* __restrict__ Wk,
                          const float* __restrict__ Wv, __half* __restrict__ d) {
    const int n = HID * 6144;
    for (int i = blockIdx.x * blockDim.x + threadIdx.x; i < n; i += gridDim.x * blockDim.x) {
        int r = i / 6144, c = i - r * 6144;
        float x;
        if (c < 4096)      x = Wq[(size_t)r * 4096 + c];
        else if (c < 5120) x = Wk[(size_t)r * 1024 + (c - 4096)];
        else               x = Wv[(size_t)r * 1024 + (c - 5120)];
        d[i] = __float2half_rn(x);
    }
}
// RoPE (q scaled, hi/lo; k hi) + V hi/lo split, one kernel.
// warp-job hh: 0..31 q-head, 32..39 k-head, 40..47 v-head.
__global__ void rope_v_kernel(const float* __restrict__ qkvf,
                              const float* __restrict__ cosb, const float* __restrict__ sinb,
                              __half* __restrict__ qh, __half* __restrict__ ql,
                              __half* __restrict__ kh,
                              __half* __restrict__ vh, __half* __restrict__ vl)
{
    int gw = blockIdx.x * 8 + (threadIdx.x >> 5);
    int lane = threadIdx.x & 31;
    int s = gw / 48, hh = gw % 48;
    if (s >= SEQ) return;

    if (hh >= 40) {   // V split
        const float* src = qkvf + (size_t)s * 6144 + 5120 + (hh - 40) * 128;
        size_t base = (size_t)s * 1024 + (hh - 40) * 128;
#pragma unroll
        for (int i = 0; i < 4; i++) {
            float x = src[i * 32 + lane];
            __half h = __float2half_rn(x);
            vh[base + i * 32 + lane] = h;
            vl[base + i * 32 + lane] = __float2half_rn(x - __half2float(h));
        }
        return;
    }

    float c0 = cosb[(size_t)s * 64 + lane];
    float s0 = sinb[(size_t)s * 64 + lane];
    float c1 = cosb[(size_t)s * 64 + 32 + lane];
    float s1 = sinb[(size_t)s * 64 + 32 + lane];

    if (hh < NH) {
        const float* src = qkvf + (size_t)s * 6144 + hh * 128;
        float x0 = src[lane], x1 = src[32 + lane], x2 = src[64 + lane], x3 = src[96 + lane];
        float v[4];
        v[0] = (x0 * c0 - x1 * s0) * SCALE;
        v[1] = (x1 * c1 + x0 * s1) * SCALE;
        v[2] = x2 * SCALE;
        v[3] = x3 * SCALE;
        size_t base = (size_t)s * 4096 + hh * 128;
        const int off[4] = {0, 32, 64, 96};
#pragma unroll
        for (int i = 0; i < 4; i++) {
            __half h = __float2half_rn(v[i]);
            qh[base + off[i] + lane] = h;
            ql[base + off[i] + lane] = __float2half_rn(v[i] - __half2float(h));
        }
    } else {
        const float* src = qkvf + (size_t)s * 6144 + 4096 + (hh - NH) * 128;
        float x0 = src[lane], x1 = src[32 + lane], x2 = src[64 + lane], x3 = src[96 + lane];
        size_t base = (size_t)s * 1024 + (hh - NH) * 128;
        kh[base + lane]      = __float2half_rn(x0 * c0 - x1 * s0);
        kh[base + 32 + lane] = __float2half_rn(x1 * c1 + x0 * s1);
        kh[base + 64 + lane] = __float2half_rn(x2);
        kh[base + 96 + lane] = __float2half_rn(x3);
    }
}

// ---------------------------------------------------------------------------
// hgemm1: C(fp32) = Ah(fp16) * B(fp16).  CTA 128x128 k32, 4 warps (2x2,
// warp 64x64), 4-stage cp.async.  stage halves: Ah 5120 | B 4352 = 9472.
// Used for BOTH the QKV projection and the O projection.
// ---------------------------------------------------------------------------
#define PSTG1 9472
#define PSMEM1 (4 * PSTG1 * 2)

__global__ __launch_bounds__(128, 3)
void hgemm1(const __half* __restrict__ Ah, const __half* __restrict__ B,
            float* __restrict__ C, int M, int N, int K, int lda, int ldb, int ldc)
{
    extern __shared__ __half sm[];
    const int bm = blockIdx.y, bn = blockIdx.x;
    const int tid = threadIdx.x, lane = tid & 31, warp = tid >> 5;
    const int wm = warp & 1, wn = warp >> 1;

    const __half* Agh = Ah + (size_t)bm * 128 * lda;
    const __half* Bg  = B + bn * 128;

    auto load_stage = [&](int st, int k0) {
        __half* sa = sm + st * PSTG1;
        __half* sb = sa + 5120;
#pragma unroll
        for (int i = 0; i < 4; i++) {
            int id = tid + i * 128;
            int r = id >> 2, u = id & 3;
            cp16(smem_u32(sa + r * 40 + u * 8), Agh + (size_t)r * lda + k0 + u * 8);
        }
#pragma unroll
        for (int i = 0; i < 4; i++) {
            int id = tid + i * 128;
            int r = id >> 4, u = id & 15;
            cp16(smem_u32(sb + r * 136 + u * 8), Bg + (size_t)(k0 + r) * ldb + u * 8);
        }
    };

    float acc[4][8][4];
#pragma unroll
    for (int a = 0; a < 4; a++)
#pragma unroll
        for (int b = 0; b < 8; b++)
#pragma unroll
            for (int c = 0; c < 4; c++) acc[a][b][c] = 0.f;

    const int nk = K >> 5;
    load_stage(0, 0);  CP_COMMIT();
    load_stage(1, 32); CP_COMMIT();
    load_stage(2, 64); CP_COMMIT();
    CP_WAIT(2);
    __syncthreads();

    for (int it = 0; it < nk; it++) {
        int nx = it + 3;
        if (nx < nk) load_stage(nx & 3, nx * 32);
        CP_COMMIT();

        const __half* sa = sm + (it & 3) * PSTG1;
        const __half* sb = sa + 5120;
#pragma unroll
        for (int kk = 0; kk < 2; kk++) {
            uint32_t ah[4][4], bb[8][2];
#pragma unroll
            for (int im = 0; im < 4; im++) {
                int r = wm * 64 + im * 16 + (lane & 15);
                int u = kk * 2 + (lane >> 4);
                ldsm4(ah[im], smem_u32(sa + r * 40 + u * 8));
            }
#pragma unroll
            for (int jp = 0; jp < 4; jp++) {
                int r = kk * 16 + (lane & 15);
                int u = wn * 8 + jp * 2 + (lane >> 4);
                uint32_t t[4];
                ldsm4t(t, smem_u32(sb + r * 136 + u * 8));
                bb[2 * jp][0] = t[0]; bb[2 * jp][1] = t[1];
                bb[2 * jp + 1][0] = t[2]; bb[2 * jp + 1][1] = t[3];
            }
#pragma unroll
            for (int im = 0; im < 4; im++)
#pragma unroll
                for (int jn = 0; jn < 8; jn++)
                    mma_f16(acc[im][jn], ah[im], bb[jn]);
        }
        CP_WAIT(2);
        __syncthreads();
    }

    const int gid = lane >> 2, tig = lane & 3;
#pragma unroll
    for (int im = 0; im < 4; im++) {
        int row = bm * 128 + wm * 64 + im * 16 + gid;
#pragma unroll
        for (int jn = 0; jn < 8; jn++) {
            int col = bn * 128 + wn * 64 + jn * 8 + tig * 2;
            *(float2*)&C[(size_t)row * ldc + col] = make_float2(acc[im][jn][0], acc[im][jn][1]);
            *(float2*)&C[(size_t)(row + 8) * ldc + col] = make_float2(acc[im][jn][2], acc[im][jn][3]);
        }
    }
}

// ---------------------------------------------------------------------------
// Flash attention, 128-wide KV tiles.  CTA: 128 q-rows (8 warps x 16),
// nkt = qt+1.  K double-buffered, Vh/Vl single-buffered.  Q/P x2 splits,
// V chains PhVh + PlVh + PhVl.  attn stored fp16 hi only.
// ---------------------------------------------------------------------------
#define FT 17408   // 128*136
#define FSMEM (6 * FT * 2)

__global__ __launch_bounds__(256, 1)
void flash_kernel(const __half* __restrict__ qh, const __half* __restrict__ ql,
                  const __half* __restrict__ kh,
                  const __half* __restrict__ vh, const __half* __restrict__ vl,
                  const float* __restrict__ sinks,
                  __half* __restrict__ ath)
{
    extern __shared__ __half sm[];
    __half* Qh = sm;
    __half* Ql = Qh + FT;
    __half* Ks = Ql + FT;        // 2 buffers
    __half* Vs = Ks + 2 * FT;    // single
    __half* Vx = Vs + FT;        // single

    const int qt = gridDim.x - 1 - blockIdx.x;
    const int h = blockIdx.y, kvh = h >> 2;
    const int tid = threadIdx.x, lane = tid & 31, w = tid >> 5;
    const int gid = lane >> 2, tig = lane & 3;

    {
        const __half* src = qh + (size_t)(qt * 128) * 4096 + h * 128;
        const __half* srl = ql + (size_t)(qt * 128) * 4096 + h * 128;
#pragma unroll
        for (int i = 0; i < 8; i++) {
            int id = tid + i * 256;
            int r = id >> 4, u = id & 15;
            cp16(smem_u32(Qh + r * 136 + u * 8), src + (size_t)r * 4096 + u * 8);
            cp16(smem_u32(Ql + r * 136 + u * 8), srl + (size_t)r * 4096 + u * 8);
        }
    }
    auto loadK = [&](int kt) {
        __half* dst = Ks + (kt & 1) * FT;
        const __half* src = kh + (size_t)(kt * 128) * 1024 + kvh * 128;
#pragma unroll
        for (int i = 0; i < 8; i++) {
            int id = tid + i * 256;
            int r = id >> 4, u = id & 15;
            cp16(smem_u32(dst + r * 136 + u * 8), src + (size_t)r * 1024 + u * 8);
        }
    };
    auto loadV = [&](int kt) {
        const __half* sv = vh + (size_t)(kt * 128) * 1024 + kvh * 128;
        const __half* sx = vl + (size_t)(kt * 128) * 1024 + kvh * 128;
#pragma unroll
        for (int i = 0; i < 8; i++) {
            int id = tid + i * 256;
            int r = id >> 4, u = id & 15;
            cp16(smem_u32(Vs + r * 136 + u * 8), sv + (size_t)r * 1024 + u * 8);
            cp16(smem_u32(Vx + r * 136 + u * 8), sx + (size_t)r * 1024 + u * 8);
        }
    };

    loadK(0);
    CP_COMMIT();     // group: Q + K0
    loadV(0);
    CP_COMMIT();     // group: V0

    float m0 = -1e30f, m1 = -1e30f, l0 = 0.f, l1 = 0.f;
    float O[16][4];
#pragma unroll
    for (int i = 0; i < 16; i++)
#pragma unroll
        for (int j = 0; j < 4; j++) O[i][j] = 0.f;

    const int nkt = qt + 1;
    const int rowg0 = qt * 128 + w * 16 + gid;

    for (int kt = 0; kt < nkt; kt++) {
        CP_WAIT(1);
        __syncthreads();

        const __half* Kb = Ks + (kt & 1) * FT;

        float S[16][4];
#pragma unroll
        for (int i = 0; i < 16; i++)
#pragma unroll
            for (int j = 0; j < 4; j++) S[i][j] = 0.f;
#pragma unroll
        for (int kk = 0; kk < 8; kk++) {
            uint32_t qa[4], qb[4], kb[16][2];
            {
                int r = w * 16 + (lane & 15);
                int u = kk * 2 + (lane >> 4);
                ldsm4(qa, smem_u32(Qh + r * 136 + u * 8));
                ldsm4(qb, smem_u32(Ql + r * 136 + u * 8));
            }
#pragma unroll
            for (int jp = 0; jp < 8; jp++) {
                int r = jp * 16 + (lane & 15);
                int u = kk * 2 + (lane >> 4);
                uint32_t t[4];
                ldsm4(t, smem_u32(Kb + r * 136 + u * 8));
                kb[2 * jp][0] = t[0]; kb[2 * jp][1] = t[2];
                kb[2 * jp + 1][0] = t[1]; kb[2 * jp + 1][1] = t[3];
            }
#pragma unroll
            for (int jn = 0; jn < 16; jn++) {
                mma_f16(S[jn], qa, kb[jn]);
                mma_f16(S[jn], qb, kb[jn]);
            }
        }

        if (kt + 1 < nkt) loadK(kt + 1);
        CP_COMMIT();

        if (kt == nkt - 1) {
#pragma unroll
            for (int jn = 0; jn < 16; jn++) {
                int colb = kt * 128 + jn * 8 + tig * 2;
                if (colb > rowg0)         S[jn][0] = -1e30f;
                if (colb + 1 > rowg0)     S[jn][1] = -1e30f;
                if (colb > rowg0 + 8)     S[jn][2] = -1e30f;
                if (colb + 1 > rowg0 + 8) S[jn][3] = -1e30f;
            }
        }

        float mr0 = -1e30f, mr1 = -1e30f;
#pragma unroll
        for (int jn = 0; jn < 16; jn++) {
            mr0 = fmaxf(mr0, fmaxf(S[jn][0], S[jn][1]));
            mr1 = fmaxf(mr1, fmaxf(S[jn][2], S[jn][3]));
        }
        mr0 = fmaxf(mr0, __shfl_xor_sync(0xffffffff, mr0, 1));
        mr0 = fmaxf(mr0, __shfl_xor_sync(0xffffffff, mr0, 2));
        mr1 = fmaxf(mr1, __shfl_xor_sync(0xffffffff, mr1, 1));
        mr1 = fmaxf(mr1, __shfl_xor_sync(0xffffffff, mr1, 2));
        float mn0 = fmaxf(m0, mr0), mn1 = fmaxf(m1, mr1);
        float a0 = __expf(m0 - mn0), a1 = __expf(m1 - mn1);

        float sum0 = 0.f, sum1 = 0.f;
#pragma unroll
        for (int jn = 0; jn < 16; jn++) {
            S[jn][0] = __expf(S[jn][0] - mn0);
            S[jn][1] = __expf(S[jn][1] - mn0);
            S[jn][2] = __expf(S[jn][2] - mn1);
            S[jn][3] = __expf(S[jn][3] - mn1);
            sum0 += S[jn][0] + S[jn][1];
            sum1 += S[jn][2] + S[jn][3];
        }
        sum0 += __shfl_xor_sync(0xffffffff, sum0, 1);
        sum0 += __shfl_xor_sync(0xffffffff, sum0, 2);
        sum1 += __shfl_xor_sync(0xffffffff, sum1, 1);
        sum1 += __shfl_xor_sync(0xffffffff, sum1, 2);
        l0 = l0 * a0 + sum0;
        l1 = l1 * a1 + sum1;
        m0 = mn0; m1 = mn1;
#pragma unroll
        for (int nt = 0; nt < 16; nt++) {
            O[nt][0] *= a0; O[nt][1] *= a0;
            O[nt][2] *= a1; O[nt][3] *= a1;
        }

        CP_WAIT(1);
        __syncthreads();

#pragma unroll
        for (int ks = 0; ks < 8; ks++) {
            uint32_t ph[4], pl[4];
#pragma unroll
            for (int t = 0; t < 2; t++) {
                float p0 = S[2 * ks + t][0], p1 = S[2 * ks + t][1];
                float p2 = S[2 * ks + t][2], p3 = S[2 * ks + t][3];
                __half h0 = __float2half_rn(p0), h1 = __float2half_rn(p1);
                __half h2 = __float2half_rn(p2), h3 = __float2half_rn(p3);
                __half2 u01; u01.x = h0; u01.y = h1;
                __half2 u23; u23.x = h2; u23.y = h3;
                ph[2 * t + 0] = *(uint32_t*)&u01;
                ph[2 * t + 1] = *(uint32_t*)&u23;
                pl[2 * t + 0] = pack_h2(p0 - __half2float(h0), p1 - __half2float(h1));
                pl[2 * t + 1] = pack_h2(p2 - __half2float(h2), p3 - __half2float(h3));
            }
            uint32_t vb[16][2];
#pragma unroll
            for (int jp = 0; jp < 8; jp++) {
                int r = ks * 16 + (lane & 15);
                int u = jp * 2 + (lane >> 4);
                uint32_t t[4];
                ldsm4t(t, smem_u32(Vs + r * 136 + u * 8));
                vb[2 * jp][0] = t[0]; vb[2 * jp][1] = t[1];
                vb[2 * jp + 1][0] = t[2]; vb[2 * jp + 1][1] = t[3];
            }
#pragma unroll
            for (int nt = 0; nt < 16; nt++) {
                mma_f16(O[nt], ph, vb[nt]);
                mma_f16(O[nt], pl, vb[nt]);
            }
#pragma unroll
            for (int jp = 0; jp < 8; jp++) {
                int r = ks * 16 + (lane & 15);
                int u = jp * 2 + (lane >> 4);
                uint32_t t[4];
                ldsm4t(t, smem_u32(Vx + r * 136 + u * 8));
                vb[2 * jp][0] = t[0]; vb[2 * jp][1] = t[1];
                vb[2 * jp + 1][0] = t[2]; vb[2 * jp + 1][1] = t[3];
            }
#pragma unroll
            for (int nt = 0; nt < 16; nt++) {
                mma_f16(O[nt], ph, vb[nt]);
            }
        }

        __syncthreads();
        if (kt + 1 < nkt) loadV(kt + 1);
        CP_COMMIT();
    }

    // ---- sink + normalize + store (hi only) ----
    float sink = sinks[h];
    l0 += __expf(sink - m0);
    l1 += __expf(sink - m1);
    float i0 = 1.f / l0, i1 = 1.f / l1;
    int row0 = qt * 128 + w * 16 + gid;
#pragma unroll
    for (int nt = 0; nt < 16; nt++) {
        int col = h * 128 + nt * 8 + tig * 2;
        float f0 = O[nt][0] * i0, f1 = O[nt][1] * i0;
        float f2 = O[nt][2] * i1, f3 = O[nt][3] * i1;
        *(uint32_t*)&ath[(size_t)row0 * 4096 + col] = pack_h2(f0, f1);
        *(uint32_t*)&ath[(size_t)(row0 + 8) * 4096 + col] = pack_h2(f2, f3);
    }
}

// ---------------------------------------------------------------------------
extern "C" void kernel_launch(void* const* d_in, const int* in_sizes, int n_in,
                              void* d_out, int out_size)
{
    const float* X_in  = (const float*)d_in[0];
    const float* cosb  = (const float*)d_in[1];
    const float* sinb  = (const float*)d_in[2];
    const float* Wq_in = (const float*)d_in[4];
    const float* Wk_in = (const float*)d_in[5];
    const float* Wv_in = (const float*)d_in[6];
    const float* Wo_in = (const float*)d_in[7];
    const float* sinks = (const float*)d_in[8];
    float* out = (float*)d_out;

    __half *Xh, *Wqkv, *Woh, *qh, *ql, *kh, *vh, *vl, *ath;
    float *qkvf;
    cudaGetSymbolAddress((void**)&Xh,   g_Xh);
    cudaGetSymbolAddress((void**)&Wqkv, g_Wqkv);
    cudaGetSymbolAddress((void**)&Woh,  g_Woh);
    cudaGetSymbolAddress((void**)&qkvf, g_qkvf);
    cudaGetSymbolAddress((void**)&qh,   g_qh);
    cudaGetSymbolAddress((void**)&ql,   g_ql);
    cudaGetSymbolAddress((void**)&kh,   g_kh);
    cudaGetSymbolAddress((void**)&vh,   g_vh);
    cudaGetSymbolAddress((void**)&vl,   g_vl);
    cudaGetSymbolAddress((void**)&ath,  g_ath);

    cudaFuncSetAttribute((const void*)hgemm1, cudaFuncAttributeMaxDynamicSharedMemorySize, PSMEM1);
    cudaFuncSetAttribute((const void*)flash_kernel, cudaFuncAttributeMaxDynamicSharedMemorySize, FSMEM);

    // 0. prep
    split1_kernel<<<2048, 256>>>(X_in, Xh, SEQ * HID);
    wqkv_pack<<<8192, 256>>>(Wq_in, Wk_in, Wv_in, Wqkv);
    split1_kernel<<<4096, 256>>>(Wo_in, Woh, 4096 * HID);

    // 1. fused QKV projection: qkvf = Xh @ Wqkv
    hgemm1<<<dim3(6144 / 128, SEQ / 128), 128, PSMEM1>>>(Xh, Wqkv, qkvf,
                                                         SEQ, 6144, HID, HID, 6144, 6144);

    // 2. RoPE + q/k/v splits (one kernel)
    rope_v_kernel<<<SEQ * 48 / 8, 256>>>(qkvf, cosb, sinb, qh, ql, kh, vh, vl);

    // 3. flash attention (128-wide KV tiles)
    flash_kernel<<<dim3(16, 32), 256, FSMEM>>>(qh, ql, kh, vh, vl, sinks, ath);

    // 4. output projection (single-A): out = ath @ Woh
    hgemm1<<<dim3(4096 / 128, SEQ / 128), 128, PSMEM1>>>(ath, Woh, out,
                                                         SEQ, HID, 4096, 4096, HID, HID);
}

// round 17
// speedup vs baseline: 1.5715x; 1.0791x over previous
#include <cuda_runtime.h>
#include <cuda_fp16.h>
#include <cstdint>

#define SEQ 2048
#define HID 4096
#define NH  32
#define NKV 8
#define HD  128
#define SCALE 0.08838834764831845f

// ---------------- scratch (device globals; no allocations) ----------------
__device__ __half g_Xh  [(size_t)SEQ * HID];
__device__ __half g_Wqkv[(size_t)HID * 6144];   // [Wq | Wk | Wv] fp16 [K,N]
__device__ __half g_Woh [(size_t)4096 * HID];   // Wo fp16 [K,N]
__device__ float  g_qkvf[(size_t)SEQ * 6144];
__device__ __half g_qh  [(size_t)SEQ * 4096];
__device__ __half g_kh  [(size_t)SEQ * 1024];
__device__ __half g_vh  [(size_t)SEQ * 1024];
__device__ __half g_vl  [(size_t)SEQ * 1024];
__device__ __half g_ath [(size_t)SEQ * 4096];

// ---------------- helpers ----------------
__device__ __forceinline__ uint32_t smem_u32(const void* p) {
    return (uint32_t)__cvta_generic_to_shared(p);
}
__device__ __forceinline__ void cp16(uint32_t s, const void* g) {
    asm volatile("cp.async.cg.shared.global [%0], [%1], 16;\n" :: "r"(s), "l"(g));
}
#define CP_COMMIT() asm volatile("cp.async.commit_group;")
#define CP_WAIT(n)  asm volatile("cp.async.wait_group %0;" :: "n"(n))

__device__ __forceinline__ void ldsm4(uint32_t* r, uint32_t a) {
    asm volatile("ldmatrix.sync.aligned.m8n8.x4.shared.b16 {%0,%1,%2,%3}, [%4];"
                 : "=r"(r[0]), "=r"(r[1]), "=r"(r[2]), "=r"(r[3]) : "r"(a));
}
__device__ __forceinline__ void ldsm4t(uint32_t* r, uint32_t a) {
    asm volatile("ldmatrix.sync.aligned.m8n8.x4.trans.shared.b16 {%0,%1,%2,%3}, [%4];"
                 : "=r"(r[0]), "=r"(r[1]), "=r"(r[2]), "=r"(r[3]) : "r"(a));
}
__device__ __forceinline__ void mma_f16(float* c, const uint32_t* a, const uint32_t* b) {
    asm volatile("mma.sync.aligned.m16n8k16.row.col.f32.f16.f16.f32 "
                 "{%0,%1,%2,%3},{%4,%5,%6,%7},{%8,%9},{%0,%1,%2,%3};"
                 : "+f"(c[0]), "+f"(c[1]), "+f"(c[2]), "+f"(c[3])
                 : "r"(a[0]), "r"(a[1]), "r"(a[2]), "r"(a[3]), "r"(b[0]), "r"(b[1]));
}
__device__ __forceinline__ uint32_t pack_h2(float a, float b) {
    __half2 t = __floats2half2_rn(a, b);
    return *reinterpret_cast<uint32_t*>(&t);
}

// ---------------- prep kernels ----------------
__global__ void split1_kernel(const float* __restrict__ s, __half* __restrict__ d, int n) {
    for (int i = blockIdx.x * blockDim.x + threadIdx.x; i < n; i += gridDim.x * blockDim.x)
        d[i] = __float2half_rn(s[i]);
}
__global__ void wqkv_pack(const float* __restrict__ Wq, const float* __restrict__ Wk,
                          const float* __restrict__ Wv, __half* __restrict__ d) {
    const int n = HID * 6144;
    for (int i = blockIdx.x * blockDim.x + threadIdx.x; i < n; i += gridDim.x * blockDim.x) {
        int r = i / 6144, c = i - r * 6144;
        float x;
        if (c < 4096)      x = Wq[(size_t)r * 4096 + c];
        else if (c < 5120) x = Wk[(size_t)r * 1024 + (c - 4096)];
        else               x = Wv[(size_t)r * 1024 + (c - 5120)];
        d[i] = __float2half_rn(x);
    }
}
// RoPE (q scaled -> hi only; k hi) + V hi/lo split, one kernel.
// warp-job hh: 0..31 q-head, 32..39 k-head, 40..47 v-head.
__global__ void rope_v_kernel(const float* __restrict__ qkvf,
                              const float* __restrict__ cosb, const float* __restrict__ sinb,
                              __half* __restrict__ qh, __half* __restrict__ kh,
                              __half* __restrict__ vh, __half* __restrict__ vl)
{
    int gw = blockIdx.x * 8 + (threadIdx.x >> 5);
    int lane = threadIdx.x & 31;
    int s = gw / 48, hh = gw % 48;
    if (s >= SEQ) return;

    if (hh >= 40) {   // V split
        const float* src = qkvf + (size_t)s * 6144 + 5120 + (hh - 40) * 128;
        size_t base = (size_t)s * 1024 + (hh - 40) * 128;
#pragma unroll
        for (int i = 0; i < 4; i++) {
            float x = src[i * 32 + lane];
            __half h = __float2half_rn(x);
            vh[base + i * 32 + lane] = h;
            vl[base + i * 32 + lane] = __float2half_rn(x - __half2float(h));
        }
        return;
    }

    float c0 = cosb[(size_t)s * 64 + lane];
    float s0 = sinb[(size_t)s * 64 + lane];
    float c1 = cosb[(size_t)s * 64 + 32 + lane];
    float s1 = sinb[(size_t)s * 64 + 32 + lane];

    if (hh < NH) {
        const float* src = qkvf + (size_t)s * 6144 + hh * 128;
        float x0 = src[lane], x1 = src[32 + lane], x2 = src[64 + lane], x3 = src[96 + lane];
        size_t base = (size_t)s * 4096 + hh * 128;
        qh[base + lane]      = __float2half_rn((x0 * c0 - x1 * s0) * SCALE);
        qh[base + 32 + lane] = __float2half_rn((x1 * c1 + x0 * s1) * SCALE);
        qh[base + 64 + lane] = __float2half_rn(x2 * SCALE);
        qh[base + 96 + lane] = __float2half_rn(x3 * SCALE);
    } else {
        const float* src = qkvf + (size_t)s * 6144 + 4096 + (hh - NH) * 128;
        float x0 = src[lane], x1 = src[32 + lane], x2 = src[64 + lane], x3 = src[96 + lane];
        size_t base = (size_t)s * 1024 + (hh - NH) * 128;
        kh[base + lane]      = __float2half_rn(x0 * c0 - x1 * s0);
        kh[base + 32 + lane] = __float2half_rn(x1 * c1 + x0 * s1);
        kh[base + 64 + lane] = __float2half_rn(x2);
        kh[base + 96 + lane] = __float2half_rn(x3);
    }
}

// ---------------------------------------------------------------------------
// hgemm1: C(fp32) = Ah(fp16) * B(fp16).  CTA 128x128 k32, 4 warps (2x2,
// warp 64x64), 4-stage cp.async.  (unchanged from R14 -- proven)
// ---------------------------------------------------------------------------
#define PSTG1 9472
#define PSMEM1 (4 * PSTG1 * 2)

__global__ __launch_bounds__(128, 3)
void hgemm1(const __half* __restrict__ Ah, const __half* __restrict__ B,
            float* __restrict__ C, int M, int N, int K, int lda, int ldb, int ldc)
{
    extern __shared__ __half sm[];
    const int bm = blockIdx.y, bn = blockIdx.x;
    const int tid = threadIdx.x, lane = tid & 31, warp = tid >> 5;
    const int wm = warp & 1, wn = warp >> 1;

    const __half* Agh = Ah + (size_t)bm * 128 * lda;
    const __half* Bg  = B + bn * 128;

    auto load_stage = [&](int st, int k0) {
        __half* sa = sm + st * PSTG1;
        __half* sb = sa + 5120;
#pragma unroll
        for (int i = 0; i < 4; i++) {
            int id = tid + i * 128;
            int r = id >> 2, u = id & 3;
            cp16(smem_u32(sa + r * 40 + u * 8), Agh + (size_t)r * lda + k0 + u * 8);
        }
#pragma unroll
        for (int i = 0; i < 4; i++) {
            int id = tid + i * 128;
            int r = id >> 4, u = id & 15;
            cp16(smem_u32(sb + r * 136 + u * 8), Bg + (size_t)(k0 + r) * ldb + u * 8);
        }
    };

    float acc[4][8][4];
#pragma unroll
    for (int a = 0; a < 4; a++)
#pragma unroll
        for (int b = 0; b < 8; b++)
#pragma unroll
            for (int c = 0; c < 4; c++) acc[a][b][c] = 0.f;

    const int nk = K >> 5;
    load_stage(0, 0);  CP_COMMIT();
    load_stage(1, 32); CP_COMMIT();
    load_stage(2, 64); CP_COMMIT();
    CP_WAIT(2);
    __syncthreads();

    for (int it = 0; it < nk; it++) {
        int nx = it + 3;
        if (nx < nk) load_stage(nx & 3, nx * 32);
        CP_COMMIT();

        const __half* sa = sm + (it & 3) * PSTG1;
        const __half* sb = sa + 5120;
#pragma unroll
        for (int kk = 0; kk < 2; kk++) {
            uint32_t ah[4][4], bb[8][2];
#pragma unroll
            for (int im = 0; im < 4; im++) {
                int r = wm * 64 + im * 16 + (lane & 15);
                int u = kk * 2 + (lane >> 4);
                ldsm4(ah[im], smem_u32(sa + r * 40 + u * 8));
            }
#pragma unroll
            for (int jp = 0; jp < 4; jp++) {
                int r = kk * 16 + (lane & 15);
                int u = wn * 8 + jp * 2 + (lane >> 4);
                uint32_t t[4];
                ldsm4t(t, smem_u32(sb + r * 136 + u * 8));
                bb[2 * jp][0] = t[0]; bb[2 * jp][1] = t[1];
                bb[2 * jp + 1][0] = t[2]; bb[2 * jp + 1][1] = t[3];
            }
#pragma unroll
            for (int im = 0; im < 4; im++)
#pragma unroll
                for (int jn = 0; jn < 8; jn++)
                    mma_f16(acc[im][jn], ah[im], bb[jn]);
        }
        CP_WAIT(2);
        __syncthreads();
    }

    const int gid = lane >> 2, tig = lane & 3;
#pragma unroll
    for (int im = 0; im < 4; im++) {
        int row = bm * 128 + wm * 64 + im * 16 + gid;
#pragma unroll
        for (int jn = 0; jn < 8; jn++) {
            int col = bn * 128 + wn * 64 + jn * 8 + tig * 2;
            *(float2*)&C[(size_t)row * ldc + col] = make_float2(acc[im][jn][0], acc[im][jn][1]);
            *(float2*)&C[(size_t)(row + 8) * ldc + col] = make_float2(acc[im][jn][2], acc[im][jn][3]);
        }
    }
}

// ---------------------------------------------------------------------------
// Flash attention, 128-wide KV tiles, fully double-buffered K AND V.
// All tiles 128x128 halves, XOR-swizzled (chunk u ^= r&7), no padding ->
// 32 KB/tile; 7 tiles (Q, 2xK, 2xVh, 2xVl) = 229376 B smem.
// Q single chain (hi only); P x2; V chains PhVh + PlVh + PhVl.
// Pipeline: tile kt+2 loads issued at end of iter kt; one CP_WAIT per tile.
// ---------------------------------------------------------------------------
#define FTS 16384   // halves per tile
#define FSMEM (7 * FTS * 2)

__device__ __forceinline__ uint32_t fswz(int r, int u) {
    return (uint32_t)(r * 128 + ((u ^ (r & 7)) << 3));
}

__global__ __launch_bounds__(256, 1)
void flash_kernel(const __half* __restrict__ qh, const __half* __restrict__ kh,
                  const __half* __restrict__ vh, const __half* __restrict__ vl,
                  const float* __restrict__ sinks,
                  __half* __restrict__ ath)
{
    extern __shared__ __half sm[];
    __half* Qs = sm;
    __half* Ks = Qs + FTS;         // 2 buffers
    __half* Vs = Ks + 2 * FTS;     // 2 buffers
    __half* Vx = Vs + 2 * FTS;     // 2 buffers

    const int qt = gridDim.x - 1 - blockIdx.x;
    const int h = blockIdx.y, kvh = h >> 2;
    const int tid = threadIdx.x, lane = tid & 31, w = tid >> 5;
    const int gid = lane >> 2, tig = lane & 3;

    auto loadQ = [&]() {
        const __half* src = qh + (size_t)(qt * 128) * 4096 + h * 128;
#pragma unroll
        for (int i = 0; i < 8; i++) {
            int id = tid + i * 256;
            int r = id >> 4, u = id & 15;
            cp16(smem_u32(Qs + fswz(r, u)), src + (size_t)r * 4096 + u * 8);
        }
    };
    auto loadK = [&](int kt) {
        __half* dst = Ks + (kt & 1) * FTS;
        const __half* src = kh + (size_t)(kt * 128) * 1024 + kvh * 128;
#pragma unroll
        for (int i = 0; i < 8; i++) {
            int id = tid + i * 256;
            int r = id >> 4, u = id & 15;
            cp16(smem_u32(dst + fswz(r, u)), src + (size_t)r * 1024 + u * 8);
        }
    };
    auto loadV = [&](int kt) {
        __half* dv = Vs + (kt & 1) * FTS;
        __half* dx = Vx + (kt & 1) * FTS;
        const __half* sv = vh + (size_t)(kt * 128) * 1024 + kvh * 128;
        const __half* sx = vl + (size_t)(kt * 128) * 1024 + kvh * 128;
#pragma unroll
        for (int i = 0; i < 8; i++) {
            int id = tid + i * 256;
            int r = id >> 4, u = id & 15;
            cp16(smem_u32(dv + fswz(r, u)), sv + (size_t)r * 1024 + u * 8);
            cp16(smem_u32(dx + fswz(r, u)), sx + (size_t)r * 1024 + u * 8);
        }
    };

    const int nkt = qt + 1;

    loadQ(); loadK(0); loadV(0);
    CP_COMMIT();                       // group 0: Q + tile0
    if (nkt > 1) { loadK(1); loadV(1); }
    CP_COMMIT();                       // group 1: tile1 (possibly empty)

    float m0 = -1e30f, m1 = -1e30f, l0 = 0.f, l1 = 0.f;
    float O[16][4];
#pragma unroll
    for (int i = 0; i < 16; i++)
#pragma unroll
        for (int j = 0; j < 4; j++) O[i][j] = 0.f;

    const int rowg0 = qt * 128 + w * 16 + gid;

    for (int kt = 0; kt < nkt; kt++) {
        CP_WAIT(1);          // tile kt resident (and Q on kt=0)
        __syncthreads();

        const __half* Kb  = Ks + (kt & 1) * FTS;
        const __half* Vb  = Vs + (kt & 1) * FTS;
        const __half* Vxb = Vx + (kt & 1) * FTS;

        // ---- S = Q K^T over 128 keys (single Q chain) ----
        float S[16][4];
#pragma unroll
        for (int i = 0; i < 16; i++)
#pragma unroll
            for (int j = 0; j < 4; j++) S[i][j] = 0.f;
#pragma unroll
        for (int kk = 0; kk < 8; kk++) {
            uint32_t qa[4], kb[16][2];
            {
                int r = w * 16 + (lane & 15);
                int u = kk * 2 + (lane >> 4);
                ldsm4(qa, smem_u32(Qs + fswz(r, u)));
            }
#pragma unroll
            for (int jp = 0; jp < 8; jp++) {
                int r = jp * 16 + (lane & 15);
                int u = kk * 2 + (lane >> 4);
                uint32_t t[4];
                ldsm4(t, smem_u32(Kb + fswz(r, u)));
                kb[2 * jp][0] = t[0]; kb[2 * jp][1] = t[2];
                kb[2 * jp + 1][0] = t[1]; kb[2 * jp + 1][1] = t[3];
            }
#pragma unroll
            for (int jn = 0; jn < 16; jn++)
                mma_f16(S[jn], qa, kb[jn]);
        }

        // ---- causal mask (diagonal tile only) ----
        if (kt == nkt - 1) {
#pragma unroll
            for (int jn = 0; jn < 16; jn++) {
                int colb = kt * 128 + jn * 8 + tig * 2;
                if (colb > rowg0)         S[jn][0] = -1e30f;
                if (colb + 1 > rowg0)     S[jn][1] = -1e30f;
                if (colb > rowg0 + 8)     S[jn][2] = -1e30f;
                if (colb + 1 > rowg0 + 8) S[jn][3] = -1e30f;
            }
        }

        // ---- online softmax ----
        float mr0 = -1e30f, mr1 = -1e30f;
#pragma unroll
        for (int jn = 0; jn < 16; jn++) {
            mr0 = fmaxf(mr0, fmaxf(S[jn][0], S[jn][1]));
            mr1 = fmaxf(mr1, fmaxf(S[jn][2], S[jn][3]));
        }
        mr0 = fmaxf(mr0, __shfl_xor_sync(0xffffffff, mr0, 1));
        mr0 = fmaxf(mr0, __shfl_xor_sync(0xffffffff, mr0, 2));
        mr1 = fmaxf(mr1, __shfl_xor_sync(0xffffffff, mr1, 1));
        mr1 = fmaxf(mr1, __shfl_xor_sync(0xffffffff, mr1, 2));
        float mn0 = fmaxf(m0, mr0), mn1 = fmaxf(m1, mr1);
        float a0 = __expf(m0 - mn0), a1 = __expf(m1 - mn1);

        float sum0 = 0.f, sum1 = 0.f;
#pragma unroll
        for (int jn = 0; jn < 16; jn++) {
            S[jn][0] = __expf(S[jn][0] - mn0);
            S[jn][1] = __expf(S[jn][1] - mn0);
            S[jn][2] = __expf(S[jn][2] - mn1);
            S[jn][3] = __expf(S[jn][3] - mn1);
            sum0 += S[jn][0] + S[jn][1];
            sum1 += S[jn][2] + S[jn][3];
        }
        sum0 += __shfl_xor_sync(0xffffffff, sum0, 1);
        sum0 += __shfl_xor_sync(0xffffffff, sum0, 2);
        sum1 += __shfl_xor_sync(0xffffffff, sum1, 1);
        sum1 += __shfl_xor_sync(0xffffffff, sum1, 2);
        l0 = l0 * a0 + sum0;
        l1 = l1 * a1 + sum1;
        m0 = mn0; m1 = mn1;
#pragma unroll
        for (int nt = 0; nt < 16; nt++) {
            O[nt][0] *= a0; O[nt][1] *= a0;
            O[nt][2] *= a1; O[nt][3] *= a1;
        }

        // ---- O += P V (P x2, V x2: PhVh + PlVh + PhVl) ----
#pragma unroll
        for (int ks = 0; ks < 8; ks++) {
            uint32_t ph[4], pl[4];
#pragma unroll
            for (int t = 0; t < 2; t++) {
                float p0 = S[2 * ks + t][0], p1 = S[2 * ks + t][1];
                float p2 = S[2 * ks + t][2], p3 = S[2 * ks + t][3];
                __half h0 = __float2half_rn(p0), h1 = __float2half_rn(p1);
                __half h2 = __float2half_rn(p2), h3 = __float2half_rn(p3);
                __half2 u01; u01.x = h0; u01.y = h1;
                __half2 u23; u23.x = h2; u23.y = h3;
                ph[2 * t + 0] = *(uint32_t*)&u01;
                ph[2 * t + 1] = *(uint32_t*)&u23;
                pl[2 * t + 0] = pack_h2(p0 - __half2float(h0), p1 - __half2float(h1));
                pl[2 * t + 1] = pack_h2(p2 - __half2float(h2), p3 - __half2float(h3));
            }
            uint32_t vb[16][2];
#pragma unroll
            for (int jp = 0; jp < 8; jp++) {
                int r = ks * 16 + (lane & 15);
                int u = jp * 2 + (lane >> 4);
                uint32_t t[4];
                ldsm4t(t, smem_u32(Vb + fswz(r, u)));
                vb[2 * jp][0] = t[0]; vb[2 * jp][1] = t[1];
                vb[2 * jp + 1][0] = t[2]; vb[2 * jp + 1][1] = t[3];
            }
#pragma unroll
            for (int nt = 0; nt < 16; nt++) {
                mma_f16(O[nt], ph, vb[nt]);
                mma_f16(O[nt], pl, vb[nt]);
            }
#pragma unroll
            for (int jp = 0; jp < 8; jp++) {
                int r = ks * 16 + (lane & 15);
                int u = jp * 2 + (lane >> 4);
                uint32_t t[4];
                ldsm4t(t, smem_u32(Vxb + fswz(r, u)));
                vb[2 * jp][0] = t[0]; vb[2 * jp][1] = t[1];
                vb[2 * jp + 1][0] = t[2]; vb[2 * jp + 1][1] = t[3];
            }
#pragma unroll
            for (int nt = 0; nt < 16; nt++)
                mma_f16(O[nt], ph, vb[nt]);
        }

        // tile kt fully consumed -> its buffers are free for tile kt+2
        __syncthreads();
        if (kt + 2 < nkt) { loadK(kt + 2); loadV(kt + 2); }
        CP_COMMIT();
    }

    // ---- sink + normalize + store (hi only) ----
    float sink = sinks[h];
    l0 += __expf(sink - m0);
    l1 += __expf(sink - m1);
    float i0 = 1.f / l0, i1 = 1.f / l1;
    int row0 = qt * 128 + w * 16 + gid;
#pragma unroll
    for (int nt = 0; nt < 16; nt++) {
        int col = h * 128 + nt * 8 + tig * 2;
        float f0 = O[nt][0] * i0, f1 = O[nt][1] * i0;
        float f2 = O[nt][2] * i1, f3 = O[nt][3] * i1;
        *(uint32_t*)&ath[(size_t)row0 * 4096 + col] = pack_h2(f0, f1);
        *(uint32_t*)&ath[(size_t)(row0 + 8) * 4096 + col] = pack_h2(f2, f3);
    }
}

// ---------------------------------------------------------------------------
extern "C" void kernel_launch(void* const* d_in, const int* in_sizes, int n_in,
                              void* d_out, int out_size)
{
    const float* X_in  = (const float*)d_in[0];
    const float* cosb  = (const float*)d_in[1];
    const float* sinb  = (const float*)d_in[2];
    const float* Wq_in = (const float*)d_in[4];
    const float* Wk_in = (const float*)d_in[5];
    const float* Wv_in = (const float*)d_in[6];
    const float* Wo_in = (const float*)d_in[7];
    const float* sinks = (const float*)d_in[8];
    float* out = (float*)d_out;

    __half *Xh, *Wqkv, *Woh, *qh, *kh, *vh, *vl, *ath;
    float *qkvf;
    cudaGetSymbolAddress((void**)&Xh,   g_Xh);
    cudaGetSymbolAddress((void**)&Wqkv, g_Wqkv);
    cudaGetSymbolAddress((void**)&Woh,  g_Woh);
    cudaGetSymbolAddress((void**)&qkvf, g_qkvf);
    cudaGetSymbolAddress((void**)&qh,   g_qh);
    cudaGetSymbolAddress((void**)&kh,   g_kh);
    cudaGetSymbolAddress((void**)&vh,   g_vh);
    cudaGetSymbolAddress((void**)&vl,   g_vl);
    cudaGetSymbolAddress((void**)&ath,  g_ath);

    cudaFuncSetAttribute((const void*)hgemm1, cudaFuncAttributeMaxDynamicSharedMemorySize, PSMEM1);
    cudaFuncSetAttribute((const void*)flash_kernel, cudaFuncAttributeMaxDynamicSharedMemorySize, FSMEM);

    // 0. prep
    split1_kernel<<<2048, 256>>>(X_in, Xh, SEQ * HID);
    wqkv_pack<<<8192, 256>>>(Wq_in, Wk_in, Wv_in, Wqkv);
    split1_kernel<<<4096, 256>>>(Wo_in, Woh, 4096 * HID);

    // 1. fused QKV projection: qkvf = Xh @ Wqkv
    hgemm1<<<dim3(6144 / 128, SEQ / 128), 128, PSMEM1>>>(Xh, Wqkv, qkvf,
                                                         SEQ, 6144, HID, HID, 6144, 6144);

    // 2. RoPE + q/k/v conversion (one kernel)
    rope_v_kernel<<<SEQ * 48 / 8, 256>>>(qkvf, cosb, sinb, qh, kh, vh, vl);

    // 3. flash attention (128-wide KV tiles, K+V double-buffered)
    flash_kernel<<<dim3(16, 32), 256, FSMEM>>>(qh, kh, vh, vl, sinks, ath);

    // 4. output projection: out = ath @ Woh
    hgemm1<<<dim3(4096 / 128, SEQ / 128), 128, PSMEM1>>>(ath, Woh, out,
                                                         SEQ, HID, 4096, 4096, HID, HID);
}